// round 1
// baseline (speedup 1.0000x reference)
#include <cuda_runtime.h>
#include <math.h>

#define NA 50000
#define NB 50000
#define NEDGE 1000000
#define LPRED 100000

// ---------------- device scratch pools (no allocations allowed) ----------------
// float pool layout (element offsets)
#define OFF_XA    0u                    // NA*256
#define OFF_XB    12800000u             // NB*256
#define OFF_HAB   25600000u             // NA*256
#define OFF_HBA   38400000u             // NB*256
#define OFF_SSAB  51200000u             // NA
#define OFF_DDAB  51250000u             // NB
#define OFF_SSBA  51300000u             // NB
#define OFF_DDBA  51350000u             // NA
#define OFF_SV    51400000u             // 4*256
#define OFF_SUM16 51401024u             // 16
#define FPOOL_N   51401040u

// int pool layout
#define IOFF_RPA  0u                    // NB+1
#define IOFF_RPB  50001u                // NA+1
#define IOFF_CNT  100002u               // 50000
#define IOFF_FILL 150002u               // 50000
#define IOFF_SRTA 200002u               // NEDGE
#define IOFF_SRTB 1200002u              // NEDGE
#define IPOOL_N   2200002u

static __device__ float g_fpool[FPOOL_N];
static __device__ int   g_ipool[IPOOL_N];

// ---------------- GEMM: C[M,N] = A[M,K] @ B[K,N], fp32, N%64==0, K%16==0 ----------------
__global__ void __launch_bounds__(256) gemm_kernel(const float* __restrict__ A,
                                                   const float* __restrict__ B,
                                                   float* __restrict__ C,
                                                   int M, int N, int K) {
    __shared__ float As[16][128];
    __shared__ float Bs[16][64];
    int tid = threadIdx.x;
    int bm = blockIdx.x * 128;
    int bn = blockIdx.y * 64;
    int ty = tid / 16, tx = tid % 16;

    float acc[8][4];
#pragma unroll
    for (int i = 0; i < 8; i++)
#pragma unroll
        for (int j = 0; j < 4; j++) acc[i][j] = 0.f;

    int aRow0 = tid / 4;           // 0..63
    int aCol  = (tid % 4) * 4;     // 0,4,8,12
    int bRow  = tid / 16;          // 0..15
    int bCol  = (tid % 16) * 4;    // 0..60

    for (int k0 = 0; k0 < K; k0 += 16) {
#pragma unroll
        for (int i = 0; i < 2; i++) {
            int r = aRow0 + i * 64;
            float4 v = make_float4(0.f, 0.f, 0.f, 0.f);
            if (bm + r < M)
                v = *(const float4*)(A + (size_t)(bm + r) * K + k0 + aCol);
            As[aCol + 0][r] = v.x;
            As[aCol + 1][r] = v.y;
            As[aCol + 2][r] = v.z;
            As[aCol + 3][r] = v.w;
        }
        {
            float4 v = *(const float4*)(B + (size_t)(k0 + bRow) * N + bn + bCol);
            *(float4*)&Bs[bRow][bCol] = v;
        }
        __syncthreads();
#pragma unroll
        for (int k = 0; k < 16; k++) {
            float ra[8], rb[4];
#pragma unroll
            for (int i = 0; i < 8; i++) ra[i] = As[k][ty * 8 + i];
#pragma unroll
            for (int j = 0; j < 4; j++) rb[j] = Bs[k][tx * 4 + j];
#pragma unroll
            for (int i = 0; i < 8; i++)
#pragma unroll
                for (int j = 0; j < 4; j++) acc[i][j] += ra[i] * rb[j];
        }
        __syncthreads();
    }
#pragma unroll
    for (int i = 0; i < 8; i++) {
        int r = bm + ty * 8 + i;
        if (r < M) {
            float4 v = make_float4(acc[i][0], acc[i][1], acc[i][2], acc[i][3]);
            *(float4*)(C + (size_t)r * N + bn + tx * 4) = v;
        }
    }
}

// ---------------- small-N GEMM: K=256, N=16 ----------------
__global__ void __launch_bounds__(512) gemm_n16_kernel(const float* __restrict__ X,
                                                       const float* __restrict__ W,
                                                       float* __restrict__ H, int M) {
    __shared__ float Ws[256 * 16];
    __shared__ float Xs[32 * 256];
    int tid = threadIdx.x;
    int row0 = blockIdx.x * 32;
    for (int i = tid; i < 256 * 16 / 4; i += 512)
        *(float4*)&Ws[i * 4] = *(const float4*)(W + i * 4);
    // load 32 rows x 256 cols = 2048 float4, 4 per thread
#pragma unroll
    for (int i = 0; i < 4; i++) {
        int lin = tid + i * 512;       // 0..2047
        int r = lin / 64;              // 0..31
        int c4 = lin % 64;             // float4 index within row
        float4 v = make_float4(0.f, 0.f, 0.f, 0.f);
        if (row0 + r < M)
            v = *(const float4*)(X + (size_t)(row0 + r) * 256 + c4 * 4);
        *(float4*)&Xs[r * 256 + c4 * 4] = v;
    }
    __syncthreads();
    int r = tid / 16, c = tid % 16;
    float acc = 0.f;
#pragma unroll 8
    for (int k = 0; k < 256; k++) acc += Xs[r * 256 + k] * Ws[k * 16 + c];
    if (row0 + r < M) H[(size_t)(row0 + r) * 16 + c] = acc;
}

// ---------------- W @ a : out[i] = sum_j W[i,j]*a[j], one warp per row ----------------
__global__ void wv_kernel(const float* __restrict__ W, const float* __restrict__ a,
                          float* __restrict__ outv, int Fin, int Fout) {
    int w = (blockIdx.x * blockDim.x + threadIdx.x) >> 5;
    int lane = threadIdx.x & 31;
    if (w >= Fin) return;
    float s = 0.f;
    for (int j = lane; j < Fout; j += 32) s += W[(size_t)w * Fout + j] * a[j];
    for (int o = 16; o; o >>= 1) s += __shfl_down_sync(0xffffffffu, s, o);
    if (lane == 0) outv[w] = s;
}

// ---------------- X @ v : one warp per row ----------------
__global__ void matvec_kernel(const float* __restrict__ X, const float* __restrict__ v,
                              float* __restrict__ outv, int M, int K) {
    int w = (blockIdx.x * blockDim.x + threadIdx.x) >> 5;
    int lane = threadIdx.x & 31;
    if (w >= M) return;
    const float* row = X + (size_t)w * K;
    float s = 0.f;
    for (int k = lane; k < K; k += 32) s += row[k] * __ldg(v + k);
    for (int o = 16; o; o >>= 1) s += __shfl_down_sync(0xffffffffu, s, o);
    if (lane == 0) outv[w] = s;
}

// ---------------- CSR build ----------------
__global__ void hist_kernel(const int* __restrict__ dst, int* __restrict__ cnt, int n) {
    int e = blockIdx.x * blockDim.x + threadIdx.x;
    if (e < n) atomicAdd(&cnt[dst[e]], 1);
}

__global__ void scan_kernel(const int* __restrict__ cnt, int* __restrict__ rowptr, int n) {
    __shared__ int sh[1024];
    __shared__ int carry;
    if (threadIdx.x == 0) { carry = 0; rowptr[0] = 0; }
    __syncthreads();
    for (int base = 0; base < n; base += 1024) {
        int i = base + threadIdx.x;
        int v = (i < n) ? cnt[i] : 0;
        sh[threadIdx.x] = v;
        __syncthreads();
        for (int off = 1; off < 1024; off <<= 1) {
            int t = (threadIdx.x >= off) ? sh[threadIdx.x - off] : 0;
            __syncthreads();
            sh[threadIdx.x] += t;
            __syncthreads();
        }
        int incl = sh[threadIdx.x] + carry;
        if (i < n) rowptr[i + 1] = incl;
        __syncthreads();
        if (threadIdx.x == 1023) carry = incl;
        __syncthreads();
    }
}

__global__ void scatter_kernel(const int* __restrict__ src, const int* __restrict__ dst,
                               const int* __restrict__ rowptr, int* __restrict__ fill,
                               int* __restrict__ sorted, int n) {
    int e = blockIdx.x * blockDim.x + threadIdx.x;
    if (e < n) {
        int d = dst[e];
        int p = rowptr[d] + atomicAdd(&fill[d], 1);
        sorted[p] = src[e];
    }
}

// ---------------- fused GAT aggregation: one warp per dst node ----------------
template <int FOUT>
__global__ void __launch_bounds__(256) gat_kernel(const int* __restrict__ rowptr,
                                                  const int* __restrict__ ssrc,
                                                  const float* __restrict__ ss,
                                                  const float* __restrict__ dd,
                                                  const float* __restrict__ H,
                                                  const float* __restrict__ bias,
                                                  float* __restrict__ out,
                                                  int ndst, int doRelu) {
    int w = (blockIdx.x * blockDim.x + threadIdx.x) >> 5;
    int lane = threadIdx.x & 31;
    if (w >= ndst) return;
    int b0 = rowptr[w], b1 = rowptr[w + 1];
    float ddv = dd[w];

    // pass 1: segment max of leaky-relu logits
    float mx = __int_as_float(0xff800000); // -inf
    for (int i = b0 + lane; i < b1; i += 32) {
        float v = __ldg(ss + ssrc[i]) + ddv;
        v = v > 0.f ? v : 0.2f * v;
        mx = fmaxf(mx, v);
    }
    for (int o = 16; o; o >>= 1) mx = fmaxf(mx, __shfl_xor_sync(0xffffffffu, mx, o));

    // pass 2: exp-sum + weighted accumulation, edges processed in warps of 32
    constexpr int NR = (FOUT + 31) / 32;
    float acc[NR];
#pragma unroll
    for (int j = 0; j < NR; j++) acc[j] = 0.f;
    float sum = 0.f;
    for (int base = b0; base < b1; base += 32) {
        int i = base + lane;
        float wgt = 0.f;
        int s = 0;
        if (i < b1) {
            s = ssrc[i];
            float v = __ldg(ss + s) + ddv;
            v = v > 0.f ? v : 0.2f * v;
            wgt = expf(v - mx);
        }
        sum += wgt;
        int nn = min(32, b1 - base);
        for (int t = 0; t < nn; t++) {
            float wt = __shfl_sync(0xffffffffu, wgt, t);
            int st = __shfl_sync(0xffffffffu, s, t);
            const float* hrow = H + (size_t)st * FOUT;
#pragma unroll
            for (int j = 0; j < NR; j++) {
                int k = lane + 32 * j;
                if (FOUT >= 32 || k < FOUT) acc[j] += wt * __ldg(hrow + k);
            }
        }
    }
    for (int o = 16; o; o >>= 1) sum += __shfl_xor_sync(0xffffffffu, sum, o);
    float inv = 1.f / (sum + 1e-16f);

    float* orow = out + (size_t)w * FOUT;
#pragma unroll
    for (int j = 0; j < NR; j++) {
        int k = lane + 32 * j;
        if (FOUT >= 32 || k < FOUT) {
            float v = acc[j] * inv + __ldg(bias + k);
            if (doRelu) v = fmaxf(v, 0.f);
            orow[k] = v;
        }
    }
}

// ---------------- readout ----------------
__global__ void sumrows16_kernel(const float* __restrict__ xb, const int* __restrict__ dstidx,
                                 float* __restrict__ out16, int L) {
    __shared__ float sh[16];
    if (threadIdx.x < 16) sh[threadIdx.x] = 0.f;
    __syncthreads();
    float loc[16];
#pragma unroll
    for (int k = 0; k < 16; k++) loc[k] = 0.f;
    for (int t = blockIdx.x * blockDim.x + threadIdx.x; t < L; t += gridDim.x * blockDim.x) {
        const float* row = xb + (size_t)dstidx[t] * 16;
#pragma unroll
        for (int k = 0; k < 16; k++) loc[k] += row[k];
    }
#pragma unroll
    for (int k = 0; k < 16; k++) atomicAdd(&sh[k], loc[k]);
    __syncthreads();
    if (threadIdx.x < 16) atomicAdd(&out16[threadIdx.x], sh[threadIdx.x]);
}

__global__ void pred_kernel(const float* __restrict__ xa, const int* __restrict__ srcidx,
                            const float* __restrict__ sum16, float* __restrict__ pred, int L) {
    int t = blockIdx.x * blockDim.x + threadIdx.x;
    if (t >= L) return;
    const float* row = xa + (size_t)srcidx[t] * 16;
    float s = 0.f;
#pragma unroll
    for (int k = 0; k < 16; k++) s += row[k] * __ldg(sum16 + k);
    pred[t] = s;
}

// ---------------- host orchestration ----------------
static inline int cdiv(int a, int b) { return (a + b - 1) / b; }

extern "C" void kernel_launch(void* const* d_in, const int* in_sizes, int n_in,
                              void* d_out, int out_size) {
    const float* xAin = (const float*)d_in[0];
    const float* xBin = (const float*)d_in[1];
    const int* ei_ab = (const int*)d_in[2];
    const int* ei_ba = (const int*)d_in[3];
    const int* srcI = (const int*)d_in[4];
    const int* dstI = (const int*)d_in[5];

    const float* Wab[3]  = {(const float*)d_in[6],  (const float*)d_in[14], (const float*)d_in[22]};
    const float* asab[3] = {(const float*)d_in[7],  (const float*)d_in[15], (const float*)d_in[23]};
    const float* adab[3] = {(const float*)d_in[8],  (const float*)d_in[16], (const float*)d_in[24]};
    const float* bab[3]  = {(const float*)d_in[9],  (const float*)d_in[17], (const float*)d_in[25]};
    const float* Wba[3]  = {(const float*)d_in[10], (const float*)d_in[18], (const float*)d_in[26]};
    const float* asba[3] = {(const float*)d_in[11], (const float*)d_in[19], (const float*)d_in[27]};
    const float* adba[3] = {(const float*)d_in[12], (const float*)d_in[20], (const float*)d_in[28]};
    const float* bba[3]  = {(const float*)d_in[13], (const float*)d_in[21], (const float*)d_in[29]};

    float* out = (float*)d_out;
    float* pred = out;
    float* xaOut = out + LPRED;
    float* xbOut = xaOut + (size_t)NA * 16;

    float* F = nullptr;
    int* I = nullptr;
    cudaGetSymbolAddress((void**)&F, g_fpool);
    cudaGetSymbolAddress((void**)&I, g_ipool);

    float* XA = F + OFF_XA;
    float* XB = F + OFF_XB;
    float* HAB = F + OFF_HAB;
    float* HBA = F + OFF_HBA;
    float* SSAB = F + OFF_SSAB;
    float* DDAB = F + OFF_DDAB;
    float* SSBA = F + OFF_SSBA;
    float* DDBA = F + OFF_DDBA;
    float* SV = F + OFF_SV;
    float* SUM16 = F + OFF_SUM16;

    int* RPA = I + IOFF_RPA;
    int* RPB = I + IOFF_RPB;
    int* CNT = I + IOFF_CNT;
    int* FILL = I + IOFF_FILL;
    int* SRTA = I + IOFF_SRTA;
    int* SRTB = I + IOFF_SRTB;

    // ---- CSR build for both directions (edge lists constant across layers) ----
    cudaMemsetAsync(CNT, 0, NB * sizeof(int), 0);
    hist_kernel<<<cdiv(NEDGE, 256), 256>>>(ei_ab + NEDGE, CNT, NEDGE);
    scan_kernel<<<1, 1024>>>(CNT, RPA, NB);
    cudaMemsetAsync(FILL, 0, NB * sizeof(int), 0);
    scatter_kernel<<<cdiv(NEDGE, 256), 256>>>(ei_ab, ei_ab + NEDGE, RPA, FILL, SRTA, NEDGE);

    cudaMemsetAsync(CNT, 0, NA * sizeof(int), 0);
    hist_kernel<<<cdiv(NEDGE, 256), 256>>>(ei_ba + NEDGE, CNT, NEDGE);
    scan_kernel<<<1, 1024>>>(CNT, RPB, NA);
    cudaMemsetAsync(FILL, 0, NA * sizeof(int), 0);
    scatter_kernel<<<cdiv(NEDGE, 256), 256>>>(ei_ba, ei_ba + NEDGE, RPB, FILL, SRTB, NEDGE);

    const int FinL[3] = {128, 256, 256};
    const int FoutL[3] = {256, 256, 16};

    for (int l = 0; l < 3; l++) {
        const float* xa = (l == 0) ? xAin : XA;
        const float* xb = (l == 0) ? xBin : XB;
        int Fin = FinL[l], Fout = FoutL[l];

        // H_src = X_src @ W for each direction
        if (Fout == 256) {
            gemm_kernel<<<dim3(cdiv(NA, 128), 256 / 64), 256>>>(xa, Wab[l], HAB, NA, 256, Fin);
            gemm_kernel<<<dim3(cdiv(NB, 128), 256 / 64), 256>>>(xb, Wba[l], HBA, NB, 256, Fin);
        } else {
            gemm_n16_kernel<<<cdiv(NA, 32), 512>>>(xa, Wab[l], HAB, NA);
            gemm_n16_kernel<<<cdiv(NB, 32), 512>>>(xb, Wba[l], HBA, NB);
        }

        // attention projection vectors: sv = W @ a_s, dv = W @ a_d (per direction)
        wv_kernel<<<cdiv(Fin, 8), 256>>>(Wab[l], asab[l], SV + 0, Fin, Fout);
        wv_kernel<<<cdiv(Fin, 8), 256>>>(Wab[l], adab[l], SV + 256, Fin, Fout);
        wv_kernel<<<cdiv(Fin, 8), 256>>>(Wba[l], asba[l], SV + 512, Fin, Fout);
        wv_kernel<<<cdiv(Fin, 8), 256>>>(Wba[l], adba[l], SV + 768, Fin, Fout);

        // per-node attention scalars
        matvec_kernel<<<cdiv(NA, 8), 256>>>(xa, SV + 0, SSAB, NA, Fin);   // ss for ab (src=A)
        matvec_kernel<<<cdiv(NB, 8), 256>>>(xb, SV + 256, DDAB, NB, Fin); // dd for ab (dst=B)
        matvec_kernel<<<cdiv(NB, 8), 256>>>(xb, SV + 512, SSBA, NB, Fin); // ss for ba (src=B)
        matvec_kernel<<<cdiv(NA, 8), 256>>>(xa, SV + 768, DDBA, NA, Fin); // dd for ba (dst=A)

        // fused softmax-aggregate (+bias, +relu). In-place overwrite of XA/XB is safe:
        // all consumers of the previous XA/XB have already run this layer.
        if (l < 2) {
            gat_kernel<256><<<cdiv(NB, 8), 256>>>(RPA, SRTA, SSAB, DDAB, HAB, bab[l], XB, NB, 1);
            gat_kernel<256><<<cdiv(NA, 8), 256>>>(RPB, SRTB, SSBA, DDBA, HBA, bba[l], XA, NA, 1);
        } else {
            gat_kernel<16><<<cdiv(NB, 8), 256>>>(RPA, SRTA, SSAB, DDAB, HAB, bab[l], xbOut, NB, 0);
            gat_kernel<16><<<cdiv(NA, 8), 256>>>(RPB, SRTB, SSBA, DDBA, HBA, bba[l], xaOut, NA, 0);
        }
    }

    // ---- readout: pred = xa[src_idx] @ sum_t xb[dst_idx[t]] ----
    cudaMemsetAsync(SUM16, 0, 16 * sizeof(float), 0);
    sumrows16_kernel<<<256, 256>>>(xbOut, dstI, SUM16, LPRED);
    pred_kernel<<<cdiv(LPRED, 256), 256>>>(xaOut, srcI, SUM16, pred, LPRED);
}

// round 4
// speedup vs baseline: 1.2323x; 1.2323x over previous
#include <cuda_runtime.h>
#include <cuda_fp16.h>
#include <math.h>

#define NA 50000
#define NB 50000
#define NEDGE 1000000
#define LPRED 100000

// ---------------- device scratch pools (no allocations allowed) ----------------
#define OFF_XA    0u                    // NA*256
#define OFF_XB    12800000u             // NB*256
#define OFF_HAB   25600000u             // NA*256
#define OFF_HBA   38400000u             // NB*256
#define OFF_SSAB  51200000u             // NA
#define OFF_DDAB  51250000u             // NB
#define OFF_SSBA  51300000u             // NB
#define OFF_DDBA  51350000u             // NA
#define OFF_SV    51400000u             // 4*256
#define OFF_SUM16 51401024u             // 16
#define OFF_WTAB  51401040u             // 256*256
#define OFF_WTBA  51466576u             // 256*256
#define FPOOL_N   51532112u

#define IOFF_RPA  0u                    // NB+1
#define IOFF_RPB  50001u                // NA+1
#define IOFF_CNT  100002u               // 50000
#define IOFF_FILL 150002u               // 50000
#define IOFF_SRTA 200002u               // NEDGE
#define IOFF_SRTB 1200002u              // NEDGE
#define IPOOL_N   2200002u

static __device__ float g_fpool[FPOOL_N];
static __device__ int   g_ipool[IPOOL_N];

// ---------------- small transpose: Wt[N][K] = W[K][N] ----------------
__global__ void transpose_kernel(const float* __restrict__ W, float* __restrict__ Wt,
                                 int K, int N) {
    __shared__ float t[32][33];
    int n0 = blockIdx.x * 32, k0 = blockIdx.y * 32;
#pragma unroll
    for (int i = 0; i < 4; i++) {
        int k = k0 + threadIdx.y + i * 8;
        t[threadIdx.y + i * 8][threadIdx.x] = W[(size_t)k * N + n0 + threadIdx.x];
    }
    __syncthreads();
#pragma unroll
    for (int i = 0; i < 4; i++) {
        int n = n0 + threadIdx.y + i * 8;
        Wt[(size_t)n * K + k0 + threadIdx.x] = t[threadIdx.x][threadIdx.y + i * 8];
    }
}

// ---------------- fp16 hi/lo split via bit truncation ----------------
__device__ __forceinline__ void split2(float x, float y, __half2* ph, __half2* pl) {
    float hx = __uint_as_float(__float_as_uint(x) & 0xFFFFE000u);
    float hy = __uint_as_float(__float_as_uint(y) & 0xFFFFE000u);
    *ph = __halves2half2(__float2half_rn(hx), __float2half_rn(hy));
    *pl = __halves2half2(__float2half_rn(x - hx), __float2half_rn(y - hy));
}

__device__ __forceinline__ void split_store4(float4 v, __half* ph, __half* pl) {
    __half2 h01, l01, h23, l23;
    split2(v.x, v.y, &h01, &l01);
    split2(v.z, v.w, &h23, &l23);
    *(__half2*)(ph)     = h01;
    *(__half2*)(ph + 2) = h23;
    *(__half2*)(pl)     = l01;
    *(__half2*)(pl + 2) = l23;
}

#define MMA_F16(cc, aa, bb)                                                         \
    asm volatile(                                                                   \
        "mma.sync.aligned.m16n8k16.row.col.f32.f16.f16.f32 "                        \
        "{%0,%1,%2,%3},{%4,%5,%6,%7},{%8,%9},{%0,%1,%2,%3};\n"                      \
        : "+f"((cc)[0]), "+f"((cc)[1]), "+f"((cc)[2]), "+f"((cc)[3])                \
        : "r"((aa)[0]), "r"((aa)[1]), "r"((aa)[2]), "r"((aa)[3]),                   \
          "r"((bb)[0]), "r"((bb)[1]))

// ---------------- tensor-core GEMM: C[M,N] = A[M,K] @ Bt[N,K]^T ----------------
__global__ void __launch_bounds__(256) gemm_f16x4_kernel(const float* __restrict__ A,
                                                         const float* __restrict__ Bt,
                                                         float* __restrict__ C,
                                                         int M, int N, int K) {
    __shared__ __half Ah[128][40], Al[128][40], Bh[128][40], Bl[128][40];
    int tid = threadIdx.x;
    int warp = tid >> 5, lane = tid & 31;
    int g = lane >> 2, tg = lane & 3;
    int wm = warp >> 2, wn = warp & 3;  // 2 x 4 warp grid
    int bm = blockIdx.x * 128, bn = blockIdx.y * 128;

    float c[4][4][4] = {};

    for (int k0 = 0; k0 < K; k0 += 32) {
#pragma unroll
        for (int i = 0; i < 4; i++) {
            int idx = tid + i * 256;
            int row = idx >> 3, k4 = (idx & 7) * 4;
            float4 v = make_float4(0.f, 0.f, 0.f, 0.f);
            int gr = bm + row;
            if (gr < M) v = *(const float4*)(A + (size_t)gr * K + k0 + k4);
            split_store4(v, &Ah[row][k4], &Al[row][k4]);
        }
#pragma unroll
        for (int i = 0; i < 4; i++) {
            int idx = tid + i * 256;
            int row = idx >> 3, k4 = (idx & 7) * 4;
            float4 v = *(const float4*)(Bt + (size_t)(bn + row) * K + k0 + k4);
            split_store4(v, &Bh[row][k4], &Bl[row][k4]);
        }
        __syncthreads();

#pragma unroll
        for (int ks = 0; ks < 2; ks++) {
            int kc = ks * 16 + tg * 2;
            unsigned ah[4][4], al[4][4], bh[4][2], bl[4][2];
#pragma unroll
            for (int mt = 0; mt < 4; mt++) {
                int r = wm * 64 + mt * 16 + g;
                ah[mt][0] = *(const unsigned*)&Ah[r][kc];
                ah[mt][1] = *(const unsigned*)&Ah[r + 8][kc];
                ah[mt][2] = *(const unsigned*)&Ah[r][kc + 8];
                ah[mt][3] = *(const unsigned*)&Ah[r + 8][kc + 8];
                al[mt][0] = *(const unsigned*)&Al[r][kc];
                al[mt][1] = *(const unsigned*)&Al[r + 8][kc];
                al[mt][2] = *(const unsigned*)&Al[r][kc + 8];
                al[mt][3] = *(const unsigned*)&Al[r + 8][kc + 8];
            }
#pragma unroll
            for (int nt = 0; nt < 4; nt++) {
                int n = wn * 32 + nt * 8 + g;
                bh[nt][0] = *(const unsigned*)&Bh[n][kc];
                bh[nt][1] = *(const unsigned*)&Bh[n][kc + 8];
                bl[nt][0] = *(const unsigned*)&Bl[n][kc];
                bl[nt][1] = *(const unsigned*)&Bl[n][kc + 8];
            }
#pragma unroll
            for (int mt = 0; mt < 4; mt++)
#pragma unroll
                for (int nt = 0; nt < 4; nt++) {
                    MMA_F16(c[mt][nt], al[mt], bl[nt]);
                    MMA_F16(c[mt][nt], ah[mt], bl[nt]);
                    MMA_F16(c[mt][nt], al[mt], bh[nt]);
                    MMA_F16(c[mt][nt], ah[mt], bh[nt]);
                }
        }
        __syncthreads();
    }

#pragma unroll
    for (int mt = 0; mt < 4; mt++) {
        int r0 = bm + wm * 64 + mt * 16 + g;
#pragma unroll
        for (int nt = 0; nt < 4; nt++) {
            int cc = bn + wn * 32 + nt * 8 + tg * 2;
            if (r0 < M)
                *(float2*)(C + (size_t)r0 * N + cc) = make_float2(c[mt][nt][0], c[mt][nt][1]);
            if (r0 + 8 < M)
                *(float2*)(C + (size_t)(r0 + 8) * N + cc) = make_float2(c[mt][nt][2], c[mt][nt][3]);
        }
    }
}

// ---------------- small-N GEMM: K=256, N=16 ----------------
__global__ void __launch_bounds__(512) gemm_n16_kernel(const float* __restrict__ X,
                                                       const float* __restrict__ W,
                                                       float* __restrict__ H, int M) {
    __shared__ float Ws[256 * 16];
    __shared__ float Xs[32 * 256];
    int tid = threadIdx.x;
    int row0 = blockIdx.x * 32;
    for (int i = tid; i < 256 * 16 / 4; i += 512)
        *(float4*)&Ws[i * 4] = *(const float4*)(W + i * 4);
#pragma unroll
    for (int i = 0; i < 4; i++) {
        int lin = tid + i * 512;
        int r = lin / 64;
        int c4 = lin % 64;
        float4 v = make_float4(0.f, 0.f, 0.f, 0.f);
        if (row0 + r < M)
            v = *(const float4*)(X + (size_t)(row0 + r) * 256 + c4 * 4);
        *(float4*)&Xs[r * 256 + c4 * 4] = v;
    }
    __syncthreads();
    int r = tid / 16, c = tid % 16;
    float acc = 0.f;
#pragma unroll 8
    for (int k = 0; k < 256; k++) acc += Xs[r * 256 + k] * Ws[k * 16 + c];
    if (row0 + r < M) H[(size_t)(row0 + r) * 16 + c] = acc;
}

// ---------------- W @ a : out[i] = sum_j W[i,j]*a[j], one warp per row ----------------
__global__ void wv_kernel(const float* __restrict__ W, const float* __restrict__ a,
                          float* __restrict__ outv, int Fin, int Fout) {
    int w = (blockIdx.x * blockDim.x + threadIdx.x) >> 5;
    int lane = threadIdx.x & 31;
    if (w >= Fin) return;
    float s = 0.f;
    for (int j = lane; j < Fout; j += 32) s += W[(size_t)w * Fout + j] * a[j];
    for (int o = 16; o; o >>= 1) s += __shfl_down_sync(0xffffffffu, s, o);
    if (lane == 0) outv[w] = s;
}

// ---------------- fused dual matvec: o1 = X@v1, o2 = X@v2 (one warp/row) ----------------
__global__ void matvec2_kernel(const float* __restrict__ X,
                               const float* __restrict__ v1, const float* __restrict__ v2,
                               float* __restrict__ o1, float* __restrict__ o2,
                               int M, int K) {
    int w = (blockIdx.x * blockDim.x + threadIdx.x) >> 5;
    int lane = threadIdx.x & 31;
    if (w >= M) return;
    const float4* row = (const float4*)(X + (size_t)w * K);
    const float4* a = (const float4*)v1;
    const float4* b = (const float4*)v2;
    float s1 = 0.f, s2 = 0.f;
    int K4 = K >> 2;
    for (int k = lane; k < K4; k += 32) {
        float4 x = row[k];
        float4 p = __ldg(a + k), q = __ldg(b + k);
        s1 += x.x * p.x + x.y * p.y + x.z * p.z + x.w * p.w;
        s2 += x.x * q.x + x.y * q.y + x.z * q.z + x.w * q.w;
    }
#pragma unroll
    for (int o = 16; o; o >>= 1) {
        s1 += __shfl_down_sync(0xffffffffu, s1, o);
        s2 += __shfl_down_sync(0xffffffffu, s2, o);
    }
    if (lane == 0) { o1[w] = s1; o2[w] = s2; }
}

// ---------------- CSR build ----------------
__global__ void hist_kernel(const int* __restrict__ dst, int* __restrict__ cnt, int n) {
    int e = blockIdx.x * blockDim.x + threadIdx.x;
    if (e < n) atomicAdd(&cnt[dst[e]], 1);
}

__global__ void scan_kernel(const int* __restrict__ cnt, int* __restrict__ rowptr, int n) {
    __shared__ int sh[1024];
    __shared__ int carry;
    if (threadIdx.x == 0) { carry = 0; rowptr[0] = 0; }
    __syncthreads();
    for (int base = 0; base < n; base += 1024) {
        int i = base + threadIdx.x;
        int v = (i < n) ? cnt[i] : 0;
        sh[threadIdx.x] = v;
        __syncthreads();
        for (int off = 1; off < 1024; off <<= 1) {
            int t = (threadIdx.x >= off) ? sh[threadIdx.x - off] : 0;
            __syncthreads();
            sh[threadIdx.x] += t;
            __syncthreads();
        }
        int incl = sh[threadIdx.x] + carry;
        if (i < n) rowptr[i + 1] = incl;
        __syncthreads();
        if (threadIdx.x == 1023) carry = incl;
        __syncthreads();
    }
}

__global__ void scatter_kernel(const int* __restrict__ src, const int* __restrict__ dst,
                               const int* __restrict__ rowptr, int* __restrict__ fill,
                               int* __restrict__ sorted, int n) {
    int e = blockIdx.x * blockDim.x + threadIdx.x;
    if (e < n) {
        int d = dst[e];
        int p = rowptr[d] + atomicAdd(&fill[d], 1);
        sorted[p] = src[e];
    }
}

// ---------------- fused GAT aggregation, FOUT=256, float4 path ----------------
__global__ void __launch_bounds__(256) gat256_kernel(const int* __restrict__ rowptr,
                                                     const int* __restrict__ ssrc,
                                                     const float* __restrict__ ss,
                                                     const float* __restrict__ dd,
                                                     const float* __restrict__ H,
                                                     const float* __restrict__ bias,
                                                     float* __restrict__ out,
                                                     int ndst, int doRelu) {
    int w = (blockIdx.x * blockDim.x + threadIdx.x) >> 5;
    int lane = threadIdx.x & 31;
    if (w >= ndst) return;
    int b0 = rowptr[w], b1 = rowptr[w + 1];
    float ddv = dd[w];

    float mx = __int_as_float(0xff800000);
    for (int i = b0 + lane; i < b1; i += 32) {
        float v = __ldg(ss + ssrc[i]) + ddv;
        v = v > 0.f ? v : 0.2f * v;
        mx = fmaxf(mx, v);
    }
#pragma unroll
    for (int o = 16; o; o >>= 1) mx = fmaxf(mx, __shfl_xor_sync(0xffffffffu, mx, o));

    float4 acc0 = make_float4(0.f, 0.f, 0.f, 0.f);
    float4 acc1 = make_float4(0.f, 0.f, 0.f, 0.f);
    float sum = 0.f;
    for (int base = b0; base < b1; base += 32) {
        int i = base + lane;
        float wgt = 0.f;
        int s = 0;
        if (i < b1) {
            s = ssrc[i];
            float v = __ldg(ss + s) + ddv;
            v = v > 0.f ? v : 0.2f * v;
            wgt = __expf(v - mx);
        }
        sum += wgt;
        int nn = min(32, b1 - base);
        for (int t = 0; t < nn; t++) {
            float wt = __shfl_sync(0xffffffffu, wgt, t);
            int st = __shfl_sync(0xffffffffu, s, t);
            const float4* h4 = (const float4*)(H + (size_t)st * 256);
            float4 v0 = __ldg(h4 + lane);
            float4 v1 = __ldg(h4 + 32 + lane);
            acc0.x += wt * v0.x; acc0.y += wt * v0.y; acc0.z += wt * v0.z; acc0.w += wt * v0.w;
            acc1.x += wt * v1.x; acc1.y += wt * v1.y; acc1.z += wt * v1.z; acc1.w += wt * v1.w;
        }
    }
#pragma unroll
    for (int o = 16; o; o >>= 1) sum += __shfl_xor_sync(0xffffffffu, sum, o);
    float inv = 1.f / (sum + 1e-16f);

    float4 bb0 = __ldg((const float4*)bias + lane);
    float4 bb1 = __ldg((const float4*)bias + 32 + lane);
    float4 o0, o1;
    o0.x = acc0.x * inv + bb0.x; o0.y = acc0.y * inv + bb0.y;
    o0.z = acc0.z * inv + bb0.z; o0.w = acc0.w * inv + bb0.w;
    o1.x = acc1.x * inv + bb1.x; o1.y = acc1.y * inv + bb1.y;
    o1.z = acc1.z * inv + bb1.z; o1.w = acc1.w * inv + bb1.w;
    if (doRelu) {
        o0.x = fmaxf(o0.x, 0.f); o0.y = fmaxf(o0.y, 0.f);
        o0.z = fmaxf(o0.z, 0.f); o0.w = fmaxf(o0.w, 0.f);
        o1.x = fmaxf(o1.x, 0.f); o1.y = fmaxf(o1.y, 0.f);
        o1.z = fmaxf(o1.z, 0.f); o1.w = fmaxf(o1.w, 0.f);
    }
    float4* orow = (float4*)(out + (size_t)w * 256);
    orow[lane] = o0;
    orow[32 + lane] = o1;
}

// ---------------- fused GAT aggregation, FOUT=16 (final layer) ----------------
__global__ void __launch_bounds__(256) gat16_kernel(const int* __restrict__ rowptr,
                                                    const int* __restrict__ ssrc,
                                                    const float* __restrict__ ss,
                                                    const float* __restrict__ dd,
                                                    const float* __restrict__ H,
                                                    const float* __restrict__ bias,
                                                    float* __restrict__ out, int ndst) {
    int w = (blockIdx.x * blockDim.x + threadIdx.x) >> 5;
    int lane = threadIdx.x & 31;
    if (w >= ndst) return;
    int b0 = rowptr[w], b1 = rowptr[w + 1];
    float ddv = dd[w];

    float mx = __int_as_float(0xff800000);
    for (int i = b0 + lane; i < b1; i += 32) {
        float v = __ldg(ss + ssrc[i]) + ddv;
        v = v > 0.f ? v : 0.2f * v;
        mx = fmaxf(mx, v);
    }
#pragma unroll
    for (int o = 16; o; o >>= 1) mx = fmaxf(mx, __shfl_xor_sync(0xffffffffu, mx, o));

    float acc = 0.f;
    float sum = 0.f;
    for (int base = b0; base < b1; base += 32) {
        int i = base + lane;
        float wgt = 0.f;
        int s = 0;
        if (i < b1) {
            s = ssrc[i];
            float v = __ldg(ss + s) + ddv;
            v = v > 0.f ? v : 0.2f * v;
            wgt = __expf(v - mx);
        }
        sum += wgt;
        int nn = min(32, b1 - base);
        for (int t = 0; t < nn; t++) {
            float wt = __shfl_sync(0xffffffffu, wgt, t);
            int st = __shfl_sync(0xffffffffu, s, t);
            if (lane < 16) acc += wt * __ldg(H + (size_t)st * 16 + lane);
        }
    }
#pragma unroll
    for (int o = 16; o; o >>= 1) sum += __shfl_xor_sync(0xffffffffu, sum, o);
    float inv = 1.f / (sum + 1e-16f);
    if (lane < 16)
        out[(size_t)w * 16 + lane] = acc * inv + __ldg(bias + lane);
}

// ---------------- readout ----------------
__global__ void sumrows16_kernel(const float* __restrict__ xb, const int* __restrict__ dstidx,
                                 float* __restrict__ out16, int L) {
    __shared__ float sh[16];
    if (threadIdx.x < 16) sh[threadIdx.x] = 0.f;
    __syncthreads();
    float loc[16];
#pragma unroll
    for (int k = 0; k < 16; k++) loc[k] = 0.f;
    for (int t = blockIdx.x * blockDim.x + threadIdx.x; t < L; t += gridDim.x * blockDim.x) {
        const float* row = xb + (size_t)dstidx[t] * 16;
#pragma unroll
        for (int k = 0; k < 16; k++) loc[k] += row[k];
    }
#pragma unroll
    for (int k = 0; k < 16; k++) atomicAdd(&sh[k], loc[k]);
    __syncthreads();
    if (threadIdx.x < 16) atomicAdd(&out16[threadIdx.x], sh[threadIdx.x]);
}

__global__ void pred_kernel(const float* __restrict__ xa, const int* __restrict__ srcidx,
                            const float* __restrict__ sum16, float* __restrict__ pred, int L) {
    int t = blockIdx.x * blockDim.x + threadIdx.x;
    if (t >= L) return;
    const float* row = xa + (size_t)srcidx[t] * 16;
    float s = 0.f;
#pragma unroll
    for (int k = 0; k < 16; k++) s += row[k] * __ldg(sum16 + k);
    pred[t] = s;
}

// ---------------- host orchestration ----------------
static inline int cdiv(int a, int b) { return (a + b - 1) / b; }

extern "C" void kernel_launch(void* const* d_in, const int* in_sizes, int n_in,
                              void* d_out, int out_size) {
    const float* xAin = (const float*)d_in[0];
    const float* xBin = (const float*)d_in[1];
    const int* ei_ab = (const int*)d_in[2];
    const int* ei_ba = (const int*)d_in[3];
    const int* srcI = (const int*)d_in[4];
    const int* dstI = (const int*)d_in[5];

    const float* Wab[3]  = {(const float*)d_in[6],  (const float*)d_in[14], (const float*)d_in[22]};
    const float* asab[3] = {(const float*)d_in[7],  (const float*)d_in[15], (const float*)d_in[23]};
    const float* adab[3] = {(const float*)d_in[8],  (const float*)d_in[16], (const float*)d_in[24]};
    const float* bab[3]  = {(const float*)d_in[9],  (const float*)d_in[17], (const float*)d_in[25]};
    const float* Wba[3]  = {(const float*)d_in[10], (const float*)d_in[18], (const float*)d_in[26]};
    const float* asba[3] = {(const float*)d_in[11], (const float*)d_in[19], (const float*)d_in[27]};
    const float* adba[3] = {(const float*)d_in[12], (const float*)d_in[20], (const float*)d_in[28]};
    const float* bba[3]  = {(const float*)d_in[13], (const float*)d_in[21], (const float*)d_in[29]};

    float* out = (float*)d_out;
    float* pred = out;
    float* xaOut = out + LPRED;
    float* xbOut = xaOut + (size_t)NA * 16;

    float* F = nullptr;
    int* I = nullptr;
    cudaGetSymbolAddress((void**)&F, g_fpool);
    cudaGetSymbolAddress((void**)&I, g_ipool);

    float* XA = F + OFF_XA;
    float* XB = F + OFF_XB;
    float* HAB = F + OFF_HAB;
    float* HBA = F + OFF_HBA;
    float* SSAB = F + OFF_SSAB;
    float* DDAB = F + OFF_DDAB;
    float* SSBA = F + OFF_SSBA;
    float* DDBA = F + OFF_DDBA;
    float* SV = F + OFF_SV;
    float* SUM16 = F + OFF_SUM16;
    float* WTAB = F + OFF_WTAB;
    float* WTBA = F + OFF_WTBA;

    int* RPA = I + IOFF_RPA;
    int* RPB = I + IOFF_RPB;
    int* CNT = I + IOFF_CNT;
    int* FILL = I + IOFF_FILL;
    int* SRTA = I + IOFF_SRTA;
    int* SRTB = I + IOFF_SRTB;

    // ---- CSR build for both directions ----
    cudaMemsetAsync(CNT, 0, NB * sizeof(int), 0);
    hist_kernel<<<cdiv(NEDGE, 256), 256>>>(ei_ab + NEDGE, CNT, NEDGE);
    scan_kernel<<<1, 1024>>>(CNT, RPA, NB);
    cudaMemsetAsync(FILL, 0, NB * sizeof(int), 0);
    scatter_kernel<<<cdiv(NEDGE, 256), 256>>>(ei_ab, ei_ab + NEDGE, RPA, FILL, SRTA, NEDGE);

    cudaMemsetAsync(CNT, 0, NA * sizeof(int), 0);
    hist_kernel<<<cdiv(NEDGE, 256), 256>>>(ei_ba + NEDGE, CNT, NEDGE);
    scan_kernel<<<1, 1024>>>(CNT, RPB, NA);
    cudaMemsetAsync(FILL, 0, NA * sizeof(int), 0);
    scatter_kernel<<<cdiv(NEDGE, 256), 256>>>(ei_ba, ei_ba + NEDGE, RPB, FILL, SRTB, NEDGE);

    const int FinL[3] = {128, 256, 256};
    const int FoutL[3] = {256, 256, 16};

    for (int l = 0; l < 3; l++) {
        const float* xa = (l == 0) ? xAin : XA;
        const float* xb = (l == 0) ? xBin : XB;
        int Fin = FinL[l], Fout = FoutL[l];

        if (l < 2) {
            transpose_kernel<<<dim3(256 / 32, Fin / 32), dim3(32, 8)>>>(Wab[l], WTAB, Fin, 256);
            transpose_kernel<<<dim3(256 / 32, Fin / 32), dim3(32, 8)>>>(Wba[l], WTBA, Fin, 256);
            gemm_f16x4_kernel<<<dim3(cdiv(NA, 128), 2), 256>>>(xa, WTAB, HAB, NA, 256, Fin);
            gemm_f16x4_kernel<<<dim3(cdiv(NB, 128), 2), 256>>>(xb, WTBA, HBA, NB, 256, Fin);
        } else {
            gemm_n16_kernel<<<cdiv(NA, 32), 512>>>(xa, Wab[l], HAB, NA);
            gemm_n16_kernel<<<cdiv(NB, 32), 512>>>(xb, Wba[l], HBA, NB);
        }

        // attention projection vectors (Fout is per-layer! 16 on the last layer)
        wv_kernel<<<cdiv(Fin, 8), 256>>>(Wab[l], asab[l], SV + 0, Fin, Fout);
        wv_kernel<<<cdiv(Fin, 8), 256>>>(Wab[l], adab[l], SV + 256, Fin, Fout);
        wv_kernel<<<cdiv(Fin, 8), 256>>>(Wba[l], asba[l], SV + 512, Fin, Fout);
        wv_kernel<<<cdiv(Fin, 8), 256>>>(Wba[l], adba[l], SV + 768, Fin, Fout);

        // per-node attention scalars (fused pairs: each X read once)
        matvec2_kernel<<<cdiv(NA, 8), 256>>>(xa, SV + 0, SV + 768, SSAB, DDBA, NA, Fin);
        matvec2_kernel<<<cdiv(NB, 8), 256>>>(xb, SV + 256, SV + 512, DDAB, SSBA, NB, Fin);

        if (l < 2) {
            gat256_kernel<<<cdiv(NB, 8), 256>>>(RPA, SRTA, SSAB, DDAB, HAB, bab[l], XB, NB, 1);
            gat256_kernel<<<cdiv(NA, 8), 256>>>(RPB, SRTB, SSBA, DDBA, HBA, bba[l], XA, NA, 1);
        } else {
            gat16_kernel<<<cdiv(NB, 8), 256>>>(RPA, SRTA, SSAB, DDAB, HAB, bab[l], xbOut, NB);
            gat16_kernel<<<cdiv(NA, 8), 256>>>(RPB, SRTB, SSBA, DDBA, HBA, bba[l], xaOut, NA);
        }
    }

    // ---- readout ----
    cudaMemsetAsync(SUM16, 0, 16 * sizeof(float), 0);
    sumrows16_kernel<<<256, 256>>>(xbOut, dstI, SUM16, LPRED);
    pred_kernel<<<cdiv(LPRED, 256), 256>>>(xaOut, srcI, SUM16, pred, LPRED);
}

// round 5
// speedup vs baseline: 1.4748x; 1.1968x over previous
#include <cuda_runtime.h>
#include <cuda_fp16.h>
#include <math.h>

#define NA 50000
#define NB 50000
#define NEDGE 1000000
#define LPRED 100000

// ---------------- device scratch pools ----------------
#define OFF_XA    0u                    // NA*256 f32
#define OFF_XB    12800000u             // NB*256 f32
#define OFF_HAB   25600000u             // NA*256 (f16 for layers 1-2, f32 for layer 3 fits too)
#define OFF_HBA   38400000u             // NB*256
#define OFF_SSAB  51200000u             // NA
#define OFF_DDAB  51250000u             // NB
#define OFF_SSBA  51300000u             // NB
#define OFF_DDBA  51350000u             // NA
#define OFF_SV    51400000u             // 4*256
#define OFF_SUM16 51401024u             // 16
#define OFF_WTAB  51401040u             // 256*256
#define OFF_WTBA  51466576u             // 256*256
#define FPOOL_N   51532112u

#define IOFF_RPA  0u                    // NB+1
#define IOFF_RPB  50001u                // NA+1
#define IOFF_CNT  100002u               // 50000
#define IOFF_FILL 150002u               // 50000
#define IOFF_SRTA 200002u               // NEDGE
#define IOFF_SRTB 1200002u              // NEDGE
#define IOFF_BSUM 2200002u              // 64
#define IPOOL_N   2200066u

static __device__ float g_fpool[FPOOL_N];
static __device__ int   g_ipool[IPOOL_N];

// ---------------- small transpose: Wt[N][K] = W[K][N] ----------------
__global__ void transpose_kernel(const float* __restrict__ W, float* __restrict__ Wt,
                                 int K, int N) {
    __shared__ float t[32][33];
    int n0 = blockIdx.x * 32, k0 = blockIdx.y * 32;
#pragma unroll
    for (int i = 0; i < 4; i++) {
        int k = k0 + threadIdx.y + i * 8;
        t[threadIdx.y + i * 8][threadIdx.x] = W[(size_t)k * N + n0 + threadIdx.x];
    }
    __syncthreads();
#pragma unroll
    for (int i = 0; i < 4; i++) {
        int n = n0 + threadIdx.y + i * 8;
        Wt[(size_t)n * K + k0 + threadIdx.x] = t[threadIdx.x][threadIdx.y + i * 8];
    }
}

// ---------------- fp16 hi/lo split via bit truncation ----------------
__device__ __forceinline__ void split2(float x, float y, __half2* ph, __half2* pl) {
    float hx = __uint_as_float(__float_as_uint(x) & 0xFFFFE000u);
    float hy = __uint_as_float(__float_as_uint(y) & 0xFFFFE000u);
    *ph = __halves2half2(__float2half_rn(hx), __float2half_rn(hy));
    *pl = __halves2half2(__float2half_rn(x - hx), __float2half_rn(y - hy));
}

__device__ __forceinline__ void split_store4(float4 v, __half* ph, __half* pl) {
    __half2 h01, l01, h23, l23;
    split2(v.x, v.y, &h01, &l01);
    split2(v.z, v.w, &h23, &l23);
    *(__half2*)(ph)     = h01;
    *(__half2*)(ph + 2) = h23;
    *(__half2*)(pl)     = l01;
    *(__half2*)(pl + 2) = l23;
}

#define MMA_F16(cc, aa, bb)                                                         \
    asm volatile(                                                                   \
        "mma.sync.aligned.m16n8k16.row.col.f32.f16.f16.f32 "                        \
        "{%0,%1,%2,%3},{%4,%5,%6,%7},{%8,%9},{%0,%1,%2,%3};\n"                      \
        : "+f"((cc)[0]), "+f"((cc)[1]), "+f"((cc)[2]), "+f"((cc)[3])                \
        : "r"((aa)[0]), "r"((aa)[1]), "r"((aa)[2]), "r"((aa)[3]),                   \
          "r"((bb)[0]), "r"((bb)[1]))

// ---------------- tensor-core GEMM: C(half)[M,N] = A[M,K] @ Bt[N,K]^T ----------------
// fp32 in, fp16 out; 3-term hi/lo emulation (hh + hl + lh); dropped ll ~2^-22.
__global__ void __launch_bounds__(256) gemm_f16x3_kernel(const float* __restrict__ A,
                                                         const float* __restrict__ Bt,
                                                         __half* __restrict__ C,
                                                         int M, int N, int K) {
    __shared__ __half Ah[128][40], Al[128][40], Bh[128][40], Bl[128][40];
    int tid = threadIdx.x;
    int warp = tid >> 5, lane = tid & 31;
    int g = lane >> 2, tg = lane & 3;
    int wm = warp >> 2, wn = warp & 3;  // 2 x 4 warp grid
    int bm = blockIdx.x * 128, bn = blockIdx.y * 128;

    float c[4][4][4] = {};

    for (int k0 = 0; k0 < K; k0 += 32) {
#pragma unroll
        for (int i = 0; i < 4; i++) {
            int idx = tid + i * 256;
            int row = idx >> 3, k4 = (idx & 7) * 4;
            float4 v = make_float4(0.f, 0.f, 0.f, 0.f);
            int gr = bm + row;
            if (gr < M) v = *(const float4*)(A + (size_t)gr * K + k0 + k4);
            split_store4(v, &Ah[row][k4], &Al[row][k4]);
        }
#pragma unroll
        for (int i = 0; i < 4; i++) {
            int idx = tid + i * 256;
            int row = idx >> 3, k4 = (idx & 7) * 4;
            float4 v = *(const float4*)(Bt + (size_t)(bn + row) * K + k0 + k4);
            split_store4(v, &Bh[row][k4], &Bl[row][k4]);
        }
        __syncthreads();

#pragma unroll
        for (int ks = 0; ks < 2; ks++) {
            int kc = ks * 16 + tg * 2;
            unsigned ah[4][4], al[4][4], bh[4][2], bl[4][2];
#pragma unroll
            for (int mt = 0; mt < 4; mt++) {
                int r = wm * 64 + mt * 16 + g;
                ah[mt][0] = *(const unsigned*)&Ah[r][kc];
                ah[mt][1] = *(const unsigned*)&Ah[r + 8][kc];
                ah[mt][2] = *(const unsigned*)&Ah[r][kc + 8];
                ah[mt][3] = *(const unsigned*)&Ah[r + 8][kc + 8];
                al[mt][0] = *(const unsigned*)&Al[r][kc];
                al[mt][1] = *(const unsigned*)&Al[r + 8][kc];
                al[mt][2] = *(const unsigned*)&Al[r][kc + 8];
                al[mt][3] = *(const unsigned*)&Al[r + 8][kc + 8];
            }
#pragma unroll
            for (int nt = 0; nt < 4; nt++) {
                int n = wn * 32 + nt * 8 + g;
                bh[nt][0] = *(const unsigned*)&Bh[n][kc];
                bh[nt][1] = *(const unsigned*)&Bh[n][kc + 8];
                bl[nt][0] = *(const unsigned*)&Bl[n][kc];
                bl[nt][1] = *(const unsigned*)&Bl[n][kc + 8];
            }
#pragma unroll
            for (int mt = 0; mt < 4; mt++)
#pragma unroll
                for (int nt = 0; nt < 4; nt++) {
                    MMA_F16(c[mt][nt], ah[mt], bl[nt]);
                    MMA_F16(c[mt][nt], al[mt], bh[nt]);
                    MMA_F16(c[mt][nt], ah[mt], bh[nt]);
                }
        }
        __syncthreads();
    }

#pragma unroll
    for (int mt = 0; mt < 4; mt++) {
        int r0 = bm + wm * 64 + mt * 16 + g;
#pragma unroll
        for (int nt = 0; nt < 4; nt++) {
            int cc = bn + wn * 32 + nt * 8 + tg * 2;
            __half2 p0 = __floats2half2_rn(c[mt][nt][0], c[mt][nt][1]);
            __half2 p1 = __floats2half2_rn(c[mt][nt][2], c[mt][nt][3]);
            if (r0 < M)     *(__half2*)(C + (size_t)r0 * N + cc) = p0;
            if (r0 + 8 < M) *(__half2*)(C + (size_t)(r0 + 8) * N + cc) = p1;
        }
    }
}

// ---------------- small-N GEMM: K=256, N=16 (fp32 out, layer 3) ----------------
__global__ void __launch_bounds__(512) gemm_n16_kernel(const float* __restrict__ X,
                                                       const float* __restrict__ W,
                                                       float* __restrict__ H, int M) {
    __shared__ float Ws[256 * 16];
    __shared__ float Xs[32 * 256];
    int tid = threadIdx.x;
    int row0 = blockIdx.x * 32;
    for (int i = tid; i < 256 * 16 / 4; i += 512)
        *(float4*)&Ws[i * 4] = *(const float4*)(W + i * 4);
#pragma unroll
    for (int i = 0; i < 4; i++) {
        int lin = tid + i * 512;
        int r = lin / 64;
        int c4 = lin % 64;
        float4 v = make_float4(0.f, 0.f, 0.f, 0.f);
        if (row0 + r < M)
            v = *(const float4*)(X + (size_t)(row0 + r) * 256 + c4 * 4);
        *(float4*)&Xs[r * 256 + c4 * 4] = v;
    }
    __syncthreads();
    int r = tid / 16, c = tid % 16;
    float acc = 0.f;
#pragma unroll 8
    for (int k = 0; k < 256; k++) acc += Xs[r * 256 + k] * Ws[k * 16 + c];
    if (row0 + r < M) H[(size_t)(row0 + r) * 16 + c] = acc;
}

// ---------------- W @ a : one warp per row ----------------
__global__ void wv_kernel(const float* __restrict__ W, const float* __restrict__ a,
                          float* __restrict__ outv, int Fin, int Fout) {
    int w = (blockIdx.x * blockDim.x + threadIdx.x) >> 5;
    int lane = threadIdx.x & 31;
    if (w >= Fin) return;
    float s = 0.f;
    for (int j = lane; j < Fout; j += 32) s += W[(size_t)w * Fout + j] * a[j];
    for (int o = 16; o; o >>= 1) s += __shfl_down_sync(0xffffffffu, s, o);
    if (lane == 0) outv[w] = s;
}

// ---------------- fused dual matvec ----------------
__global__ void matvec2_kernel(const float* __restrict__ X,
                               const float* __restrict__ v1, const float* __restrict__ v2,
                               float* __restrict__ o1, float* __restrict__ o2,
                               int M, int K) {
    int w = (blockIdx.x * blockDim.x + threadIdx.x) >> 5;
    int lane = threadIdx.x & 31;
    if (w >= M) return;
    const float4* row = (const float4*)(X + (size_t)w * K);
    const float4* a = (const float4*)v1;
    const float4* b = (const float4*)v2;
    float s1 = 0.f, s2 = 0.f;
    int K4 = K >> 2;
    for (int k = lane; k < K4; k += 32) {
        float4 x = row[k];
        float4 p = __ldg(a + k), q = __ldg(b + k);
        s1 += x.x * p.x + x.y * p.y + x.z * p.z + x.w * p.w;
        s2 += x.x * q.x + x.y * q.y + x.z * q.z + x.w * q.w;
    }
#pragma unroll
    for (int o = 16; o; o >>= 1) {
        s1 += __shfl_down_sync(0xffffffffu, s1, o);
        s2 += __shfl_down_sync(0xffffffffu, s2, o);
    }
    if (lane == 0) { o1[w] = s1; o2[w] = s2; }
}

// ---------------- CSR build ----------------
__global__ void hist_kernel(const int* __restrict__ dst, int* __restrict__ cnt, int n) {
    int e = blockIdx.x * blockDim.x + threadIdx.x;
    if (e < n) atomicAdd(&cnt[dst[e]], 1);
}

// multi-block scan: phase 1 (per-block inclusive scan + block sums)
__global__ void scan1_kernel(const int* __restrict__ cnt, int* __restrict__ rowptr,
                             int* __restrict__ bsum, int n) {
    __shared__ int sh[1024];
    int i = blockIdx.x * 1024 + threadIdx.x;
    int v = (i < n) ? cnt[i] : 0;
    sh[threadIdx.x] = v;
    __syncthreads();
    for (int off = 1; off < 1024; off <<= 1) {
        int t = (threadIdx.x >= off) ? sh[threadIdx.x - off] : 0;
        __syncthreads();
        sh[threadIdx.x] += t;
        __syncthreads();
    }
    if (i < n) rowptr[i + 1] = sh[threadIdx.x];
    if (threadIdx.x == 1023) bsum[blockIdx.x] = sh[1023];
}

// phase 2: exclusive scan of block sums (nb <= 64)
__global__ void scan2_kernel(int* __restrict__ bsum, int nb) {
    if (threadIdx.x == 0) {
        int run = 0;
        for (int k = 0; k < nb; k++) { int c = bsum[k]; bsum[k] = run; run += c; }
    }
}

// phase 3: add block offsets
__global__ void scan3_kernel(int* __restrict__ rowptr, const int* __restrict__ bsum, int n) {
    int i = blockIdx.x * 1024 + threadIdx.x;
    if (i < n) rowptr[i + 1] += bsum[blockIdx.x];
    if (i == 0) rowptr[0] = 0;
}

__global__ void scatter_kernel(const int* __restrict__ src, const int* __restrict__ dst,
                               const int* __restrict__ rowptr, int* __restrict__ fill,
                               int* __restrict__ sorted, int n) {
    int e = blockIdx.x * blockDim.x + threadIdx.x;
    if (e < n) {
        int d = dst[e];
        int p = rowptr[d] + atomicAdd(&fill[d], 1);
        sorted[p] = src[e];
    }
}

// ---------------- fused GAT aggregation, FOUT=256, fp16 H gather ----------------
__global__ void __launch_bounds__(256) gat256h_kernel(const int* __restrict__ rowptr,
                                                      const int* __restrict__ ssrc,
                                                      const float* __restrict__ ss,
                                                      const float* __restrict__ dd,
                                                      const __half* __restrict__ H,
                                                      const float* __restrict__ bias,
                                                      float* __restrict__ out,
                                                      int ndst, int doRelu) {
    int w = (blockIdx.x * blockDim.x + threadIdx.x) >> 5;
    int lane = threadIdx.x & 31;
    if (w >= ndst) return;
    int b0 = rowptr[w], b1 = rowptr[w + 1];
    float ddv = dd[w];

    // pass 1: segment max of leaky-relu logits
    float mx = __int_as_float(0xff800000);
    for (int i = b0 + lane; i < b1; i += 32) {
        float v = __ldg(ss + ssrc[i]) + ddv;
        v = v > 0.f ? v : 0.2f * v;
        mx = fmaxf(mx, v);
    }
#pragma unroll
    for (int o = 16; o; o >>= 1) mx = fmaxf(mx, __shfl_xor_sync(0xffffffffu, mx, o));

    // pass 2: exp-sum + weighted fp16 gather (8 features per lane, 1 LDG.128 per edge)
    float acc[8] = {};
    float sum = 0.f;
    for (int base = b0; base < b1; base += 32) {
        int i = base + lane;
        float wgt = 0.f;
        int s = 0;
        if (i < b1) {
            s = ssrc[i];
            float v = __ldg(ss + s) + ddv;
            v = v > 0.f ? v : 0.2f * v;
            wgt = __expf(v - mx);
        }
        sum += wgt;
        int nn = min(32, b1 - base);
        for (int t = 0; t < nn; t++) {
            float wt = __shfl_sync(0xffffffffu, wgt, t);
            int st = __shfl_sync(0xffffffffu, s, t);
            uint4 u = __ldg((const uint4*)(H + (size_t)st * 256) + lane);
            const __half2* hh = (const __half2*)&u;
#pragma unroll
            for (int j = 0; j < 4; j++) {
                float2 f = __half22float2(hh[j]);
                acc[2 * j]     += wt * f.x;
                acc[2 * j + 1] += wt * f.y;
            }
        }
    }
#pragma unroll
    for (int o = 16; o; o >>= 1) sum += __shfl_xor_sync(0xffffffffu, sum, o);
    float inv = 1.f / (sum + 1e-16f);

    // lane owns features [lane*8, lane*8+8)
    float4 bb0 = __ldg((const float4*)bias + lane * 2);
    float4 bb1 = __ldg((const float4*)bias + lane * 2 + 1);
    float4 o0, o1;
    o0.x = acc[0] * inv + bb0.x; o0.y = acc[1] * inv + bb0.y;
    o0.z = acc[2] * inv + bb0.z; o0.w = acc[3] * inv + bb0.w;
    o1.x = acc[4] * inv + bb1.x; o1.y = acc[5] * inv + bb1.y;
    o1.z = acc[6] * inv + bb1.z; o1.w = acc[7] * inv + bb1.w;
    if (doRelu) {
        o0.x = fmaxf(o0.x, 0.f); o0.y = fmaxf(o0.y, 0.f);
        o0.z = fmaxf(o0.z, 0.f); o0.w = fmaxf(o0.w, 0.f);
        o1.x = fmaxf(o1.x, 0.f); o1.y = fmaxf(o1.y, 0.f);
        o1.z = fmaxf(o1.z, 0.f); o1.w = fmaxf(o1.w, 0.f);
    }
    float4* orow = (float4*)(out + (size_t)w * 256);
    orow[lane * 2]     = o0;
    orow[lane * 2 + 1] = o1;
}

// ---------------- fused GAT aggregation, FOUT=16 (final layer, fp32 H) ----------------
__global__ void __launch_bounds__(256) gat16_kernel(const int* __restrict__ rowptr,
                                                    const int* __restrict__ ssrc,
                                                    const float* __restrict__ ss,
                                                    const float* __restrict__ dd,
                                                    const float* __restrict__ H,
                                                    const float* __restrict__ bias,
                                                    float* __restrict__ out, int ndst) {
    int w = (blockIdx.x * blockDim.x + threadIdx.x) >> 5;
    int lane = threadIdx.x & 31;
    if (w >= ndst) return;
    int b0 = rowptr[w], b1 = rowptr[w + 1];
    float ddv = dd[w];

    float mx = __int_as_float(0xff800000);
    for (int i = b0 + lane; i < b1; i += 32) {
        float v = __ldg(ss + ssrc[i]) + ddv;
        v = v > 0.f ? v : 0.2f * v;
        mx = fmaxf(mx, v);
    }
#pragma unroll
    for (int o = 16; o; o >>= 1) mx = fmaxf(mx, __shfl_xor_sync(0xffffffffu, mx, o));

    float acc = 0.f;
    float sum = 0.f;
    for (int base = b0; base < b1; base += 32) {
        int i = base + lane;
        float wgt = 0.f;
        int s = 0;
        if (i < b1) {
            s = ssrc[i];
            float v = __ldg(ss + s) + ddv;
            v = v > 0.f ? v : 0.2f * v;
            wgt = __expf(v - mx);
        }
        sum += wgt;
        int nn = min(32, b1 - base);
        for (int t = 0; t < nn; t++) {
            float wt = __shfl_sync(0xffffffffu, wgt, t);
            int st = __shfl_sync(0xffffffffu, s, t);
            if (lane < 16) acc += wt * __ldg(H + (size_t)st * 16 + lane);
        }
    }
#pragma unroll
    for (int o = 16; o; o >>= 1) sum += __shfl_xor_sync(0xffffffffu, sum, o);
    float inv = 1.f / (sum + 1e-16f);
    if (lane < 16)
        out[(size_t)w * 16 + lane] = acc * inv + __ldg(bias + lane);
}

// ---------------- readout ----------------
__global__ void sumrows16_kernel(const float* __restrict__ xb, const int* __restrict__ dstidx,
                                 float* __restrict__ out16, int L) {
    __shared__ float sh[16];
    if (threadIdx.x < 16) sh[threadIdx.x] = 0.f;
    __syncthreads();
    float loc[16];
#pragma unroll
    for (int k = 0; k < 16; k++) loc[k] = 0.f;
    for (int t = blockIdx.x * blockDim.x + threadIdx.x; t < L; t += gridDim.x * blockDim.x) {
        const float* row = xb + (size_t)dstidx[t] * 16;
#pragma unroll
        for (int k = 0; k < 16; k++) loc[k] += row[k];
    }
#pragma unroll
    for (int k = 0; k < 16; k++) atomicAdd(&sh[k], loc[k]);
    __syncthreads();
    if (threadIdx.x < 16) atomicAdd(&out16[threadIdx.x], sh[threadIdx.x]);
}

__global__ void pred_kernel(const float* __restrict__ xa, const int* __restrict__ srcidx,
                            const float* __restrict__ sum16, float* __restrict__ pred, int L) {
    int t = blockIdx.x * blockDim.x + threadIdx.x;
    if (t >= L) return;
    const float* row = xa + (size_t)srcidx[t] * 16;
    float s = 0.f;
#pragma unroll
    for (int k = 0; k < 16; k++) s += row[k] * __ldg(sum16 + k);
    pred[t] = s;
}

// ---------------- host orchestration ----------------
static inline int cdiv(int a, int b) { return (a + b - 1) / b; }

extern "C" void kernel_launch(void* const* d_in, const int* in_sizes, int n_in,
                              void* d_out, int out_size) {
    const float* xAin = (const float*)d_in[0];
    const float* xBin = (const float*)d_in[1];
    const int* ei_ab = (const int*)d_in[2];
    const int* ei_ba = (const int*)d_in[3];
    const int* srcI = (const int*)d_in[4];
    const int* dstI = (const int*)d_in[5];

    const float* Wab[3]  = {(const float*)d_in[6],  (const float*)d_in[14], (const float*)d_in[22]};
    const float* asab[3] = {(const float*)d_in[7],  (const float*)d_in[15], (const float*)d_in[23]};
    const float* adab[3] = {(const float*)d_in[8],  (const float*)d_in[16], (const float*)d_in[24]};
    const float* bab[3]  = {(const float*)d_in[9],  (const float*)d_in[17], (const float*)d_in[25]};
    const float* Wba[3]  = {(const float*)d_in[10], (const float*)d_in[18], (const float*)d_in[26]};
    const float* asba[3] = {(const float*)d_in[11], (const float*)d_in[19], (const float*)d_in[27]};
    const float* adba[3] = {(const float*)d_in[12], (const float*)d_in[20], (const float*)d_in[28]};
    const float* bba[3]  = {(const float*)d_in[13], (const float*)d_in[21], (const float*)d_in[29]};

    float* out = (float*)d_out;
    float* pred = out;
    float* xaOut = out + LPRED;
    float* xbOut = xaOut + (size_t)NA * 16;

    float* F = nullptr;
    int* I = nullptr;
    cudaGetSymbolAddress((void**)&F, g_fpool);
    cudaGetSymbolAddress((void**)&I, g_ipool);

    float* XA = F + OFF_XA;
    float* XB = F + OFF_XB;
    float* HABf = F + OFF_HAB;           // fp32 view (layer 3)
    float* HBAf = F + OFF_HBA;
    __half* HABh = (__half*)(F + OFF_HAB); // fp16 view (layers 1-2)
    __half* HBAh = (__half*)(F + OFF_HBA);
    float* SSAB = F + OFF_SSAB;
    float* DDAB = F + OFF_DDAB;
    float* SSBA = F + OFF_SSBA;
    float* DDBA = F + OFF_DDBA;
    float* SV = F + OFF_SV;
    float* SUM16 = F + OFF_SUM16;
    float* WTAB = F + OFF_WTAB;
    float* WTBA = F + OFF_WTBA;

    int* RPA = I + IOFF_RPA;
    int* RPB = I + IOFF_RPB;
    int* CNT = I + IOFF_CNT;
    int* FILL = I + IOFF_FILL;
    int* SRTA = I + IOFF_SRTA;
    int* SRTB = I + IOFF_SRTB;
    int* BSUM = I + IOFF_BSUM;

    const int nScanBlk = cdiv(NB, 1024); // NA == NB == 50000

    // ---- CSR build, direction ab (dst in B) ----
    cudaMemsetAsync(CNT, 0, NB * sizeof(int), 0);
    hist_kernel<<<cdiv(NEDGE, 256), 256>>>(ei_ab + NEDGE, CNT, NEDGE);
    scan1_kernel<<<nScanBlk, 1024>>>(CNT, RPA, BSUM, NB);
    scan2_kernel<<<1, 32>>>(BSUM, nScanBlk);
    scan3_kernel<<<nScanBlk, 1024>>>(RPA, BSUM, NB);
    cudaMemsetAsync(FILL, 0, NB * sizeof(int), 0);
    scatter_kernel<<<cdiv(NEDGE, 256), 256>>>(ei_ab, ei_ab + NEDGE, RPA, FILL, SRTA, NEDGE);

    // ---- CSR build, direction ba (dst in A) ----
    cudaMemsetAsync(CNT, 0, NA * sizeof(int), 0);
    hist_kernel<<<cdiv(NEDGE, 256), 256>>>(ei_ba + NEDGE, CNT, NEDGE);
    scan1_kernel<<<nScanBlk, 1024>>>(CNT, RPB, BSUM, NA);
    scan2_kernel<<<1, 32>>>(BSUM, nScanBlk);
    scan3_kernel<<<nScanBlk, 1024>>>(RPB, BSUM, NA);
    cudaMemsetAsync(FILL, 0, NA * sizeof(int), 0);
    scatter_kernel<<<cdiv(NEDGE, 256), 256>>>(ei_ba, ei_ba + NEDGE, RPB, FILL, SRTB, NEDGE);

    const int FinL[3] = {128, 256, 256};
    const int FoutL[3] = {256, 256, 16};

    for (int l = 0; l < 3; l++) {
        const float* xa = (l == 0) ? xAin : XA;
        const float* xb = (l == 0) ? xBin : XB;
        int Fin = FinL[l], Fout = FoutL[l];

        if (l < 2) {
            transpose_kernel<<<dim3(256 / 32, Fin / 32), dim3(32, 8)>>>(Wab[l], WTAB, Fin, 256);
            transpose_kernel<<<dim3(256 / 32, Fin / 32), dim3(32, 8)>>>(Wba[l], WTBA, Fin, 256);
            gemm_f16x3_kernel<<<dim3(cdiv(NA, 128), 2), 256>>>(xa, WTAB, HABh, NA, 256, Fin);
            gemm_f16x3_kernel<<<dim3(cdiv(NB, 128), 2), 256>>>(xb, WTBA, HBAh, NB, 256, Fin);
        } else {
            gemm_n16_kernel<<<cdiv(NA, 32), 512>>>(xa, Wab[l], HABf, NA);
            gemm_n16_kernel<<<cdiv(NB, 32), 512>>>(xb, Wba[l], HBAf, NB);
        }

        // attention projection vectors (Fout per layer)
        wv_kernel<<<cdiv(Fin, 8), 256>>>(Wab[l], asab[l], SV + 0, Fin, Fout);
        wv_kernel<<<cdiv(Fin, 8), 256>>>(Wab[l], adab[l], SV + 256, Fin, Fout);
        wv_kernel<<<cdiv(Fin, 8), 256>>>(Wba[l], asba[l], SV + 512, Fin, Fout);
        wv_kernel<<<cdiv(Fin, 8), 256>>>(Wba[l], adba[l], SV + 768, Fin, Fout);

        // per-node attention scalars
        matvec2_kernel<<<cdiv(NA, 8), 256>>>(xa, SV + 0, SV + 768, SSAB, DDBA, NA, Fin);
        matvec2_kernel<<<cdiv(NB, 8), 256>>>(xb, SV + 256, SV + 512, DDAB, SSBA, NB, Fin);

        if (l < 2) {
            gat256h_kernel<<<cdiv(NB, 8), 256>>>(RPA, SRTA, SSAB, DDAB, HABh, bab[l], XB, NB, 1);
            gat256h_kernel<<<cdiv(NA, 8), 256>>>(RPB, SRTB, SSBA, DDBA, HBAh, bba[l], XA, NA, 1);
        } else {
            gat16_kernel<<<cdiv(NB, 8), 256>>>(RPA, SRTA, SSAB, DDAB, HABf, bab[l], xbOut, NB);
            gat16_kernel<<<cdiv(NA, 8), 256>>>(RPB, SRTB, SSBA, DDBA, HBAf, bba[l], xaOut, NA);
        }
    }

    // ---- readout ----
    cudaMemsetAsync(SUM16, 0, 16 * sizeof(float), 0);
    sumrows16_kernel<<<256, 256>>>(xbOut, dstI, SUM16, LPRED);
    pred_kernel<<<cdiv(LPRED, 256), 256>>>(xaOut, srcI, SUM16, pred, LPRED);
}

// round 6
// speedup vs baseline: 1.5868x; 1.0760x over previous
#include <cuda_runtime.h>
#include <cuda_fp16.h>
#include <math.h>

#define NA 50000
#define NB 50000
#define NEDGE 1000000
#define LPRED 100000

// ---------------- device scratch pools ----------------
#define OFF_XA    0u                    // NA*256 f32
#define OFF_XB    12800000u             // NB*256 f32
#define OFF_HAB   25600000u             // NA*256 (f16 layers 1-2 / f32 layer 3)
#define OFF_HBA   38400000u             // NB*256
#define OFF_SSAB  51200000u             // NA
#define OFF_DDAB  51250000u             // NB
#define OFF_SSBA  51300000u             // NB
#define OFF_DDBA  51350000u             // NA
#define OFF_SV    51400000u             // 2*256 (dv projections)
#define OFF_SUM16 51401024u             // 16
#define OFF_WTAB  51401040u             // 256*256
#define OFF_WTBA  51466576u             // 256*256
#define FPOOL_N   51532112u

// ints: concatenated 2-direction CSR
#define IOFF_RP2   0u                   // 100001 (ab rows 0..50000, ba rows 50000..100000)
#define IOFF_CNT2  100001u              // 100000
#define IOFF_FILL2 200001u              // 100000
#define IOFF_SRT   300001u              // 2*NEDGE
#define IOFF_BSUM  2300001u             // 128
#define IPOOL_N    2300129u

static __device__ float g_fpool[FPOOL_N];
static __device__ int   g_ipool[IPOOL_N];

// ---------------- fused transpose: Wt[N][K] = W[K][N], 2 matrices ----------------
__global__ void transpose2_kernel(const float* __restrict__ W0, float* __restrict__ T0,
                                  const float* __restrict__ W1, float* __restrict__ T1,
                                  int K, int N) {
    __shared__ float t[32][33];
    const float* W = blockIdx.z ? W1 : W0;
    float* Wt = blockIdx.z ? T1 : T0;
    int n0 = blockIdx.x * 32, k0 = blockIdx.y * 32;
#pragma unroll
    for (int i = 0; i < 4; i++) {
        int k = k0 + threadIdx.y + i * 8;
        t[threadIdx.y + i * 8][threadIdx.x] = W[(size_t)k * N + n0 + threadIdx.x];
    }
    __syncthreads();
#pragma unroll
    for (int i = 0; i < 4; i++) {
        int n = n0 + threadIdx.y + i * 8;
        Wt[(size_t)n * K + k0 + threadIdx.x] = t[threadIdx.x][threadIdx.y + i * 8];
    }
}

// ---------------- fp16 hi/lo split via bit truncation ----------------
__device__ __forceinline__ void split2(float x, float y, __half2* ph, __half2* pl) {
    float hx = __uint_as_float(__float_as_uint(x) & 0xFFFFE000u);
    float hy = __uint_as_float(__float_as_uint(y) & 0xFFFFE000u);
    *ph = __halves2half2(__float2half_rn(hx), __float2half_rn(hy));
    *pl = __halves2half2(__float2half_rn(x - hx), __float2half_rn(y - hy));
}

__device__ __forceinline__ void split_store4(float4 v, __half* ph, __half* pl) {
    __half2 h01, l01, h23, l23;
    split2(v.x, v.y, &h01, &l01);
    split2(v.z, v.w, &h23, &l23);
    *(__half2*)(ph)     = h01;
    *(__half2*)(ph + 2) = h23;
    *(__half2*)(pl)     = l01;
    *(__half2*)(pl + 2) = l23;
}

#define MMA_F16(cc, aa, bb)                                                         \
    asm volatile(                                                                   \
        "mma.sync.aligned.m16n8k16.row.col.f32.f16.f16.f32 "                        \
        "{%0,%1,%2,%3},{%4,%5,%6,%7},{%8,%9},{%0,%1,%2,%3};\n"                      \
        : "+f"((cc)[0]), "+f"((cc)[1]), "+f"((cc)[2]), "+f"((cc)[3])                \
        : "r"((aa)[0]), "r"((aa)[1]), "r"((aa)[2]), "r"((aa)[3]),                   \
          "r"((bb)[0]), "r"((bb)[1]))

// ---------------- tensor-core GEMM with fused attention scalars ----------------
// C(half)[M,N] = A[M,K] @ Bt[N,K]^T ; 3-term fp16 hi/lo emulation.
// Additionally: ssOut[r] += sum_c C[r,c]*sv[c]  (atomicAdd across the 2 N-blocks)
//               ddOut[r]  = sum_k A[r,k]*dv[k]  (bn==0 block only, direct store)
__global__ void __launch_bounds__(256) gemm_f16x3_kernel(const float* __restrict__ A,
                                                         const float* __restrict__ Bt,
                                                         __half* __restrict__ C,
                                                         int M, int N, int K,
                                                         const float* __restrict__ sv,
                                                         const float* __restrict__ dv,
                                                         float* __restrict__ ssOut,
                                                         float* __restrict__ ddOut) {
    __shared__ __half Ah[128][40], Al[128][40], Bh[128][40], Bl[128][40];
    __shared__ float ssred[128];
    int tid = threadIdx.x;
    int warp = tid >> 5, lane = tid & 31;
    int g = lane >> 2, tg = lane & 3;
    int wm = warp >> 2, wn = warp & 3;  // 2 x 4 warp grid
    int bm = blockIdx.x * 128, bn = blockIdx.y * 128;

    float c[4][4][4] = {};
    float dacc[4] = {0.f, 0.f, 0.f, 0.f};

    for (int k0 = 0; k0 < K; k0 += 32) {
        float4 dv4 = __ldg((const float4*)(dv + k0) + (tid & 7));
#pragma unroll
        for (int i = 0; i < 4; i++) {
            int idx = tid + i * 256;
            int row = idx >> 3, k4 = (idx & 7) * 4;
            float4 v = make_float4(0.f, 0.f, 0.f, 0.f);
            int gr = bm + row;
            if (gr < M) v = *(const float4*)(A + (size_t)gr * K + k0 + k4);
            dacc[i] += v.x * dv4.x + v.y * dv4.y + v.z * dv4.z + v.w * dv4.w;
            split_store4(v, &Ah[row][k4], &Al[row][k4]);
        }
#pragma unroll
        for (int i = 0; i < 4; i++) {
            int idx = tid + i * 256;
            int row = idx >> 3, k4 = (idx & 7) * 4;
            float4 v = *(const float4*)(Bt + (size_t)(bn + row) * K + k0 + k4);
            split_store4(v, &Bh[row][k4], &Bl[row][k4]);
        }
        __syncthreads();

#pragma unroll
        for (int ks = 0; ks < 2; ks++) {
            int kc = ks * 16 + tg * 2;
            unsigned ah[4][4], al[4][4], bh[4][2], bl[4][2];
#pragma unroll
            for (int mt = 0; mt < 4; mt++) {
                int r = wm * 64 + mt * 16 + g;
                ah[mt][0] = *(const unsigned*)&Ah[r][kc];
                ah[mt][1] = *(const unsigned*)&Ah[r + 8][kc];
                ah[mt][2] = *(const unsigned*)&Ah[r][kc + 8];
                ah[mt][3] = *(const unsigned*)&Ah[r + 8][kc + 8];
                al[mt][0] = *(const unsigned*)&Al[r][kc];
                al[mt][1] = *(const unsigned*)&Al[r + 8][kc];
                al[mt][2] = *(const unsigned*)&Al[r][kc + 8];
                al[mt][3] = *(const unsigned*)&Al[r + 8][kc + 8];
            }
#pragma unroll
            for (int nt = 0; nt < 4; nt++) {
                int n = wn * 32 + nt * 8 + g;
                bh[nt][0] = *(const unsigned*)&Bh[n][kc];
                bh[nt][1] = *(const unsigned*)&Bh[n][kc + 8];
                bl[nt][0] = *(const unsigned*)&Bl[n][kc];
                bl[nt][1] = *(const unsigned*)&Bl[n][kc + 8];
            }
#pragma unroll
            for (int mt = 0; mt < 4; mt++)
#pragma unroll
                for (int nt = 0; nt < 4; nt++) {
                    MMA_F16(c[mt][nt], ah[mt], bl[nt]);
                    MMA_F16(c[mt][nt], al[mt], bh[nt]);
                    MMA_F16(c[mt][nt], ah[mt], bh[nt]);
                }
        }
        __syncthreads();
    }

    // dd: reduce dacc over the 8 lanes sharing a row (same lane>>3 group)
    if (blockIdx.y == 0) {
#pragma unroll
        for (int i = 0; i < 4; i++) {
            float v = dacc[i];
            v += __shfl_xor_sync(0xffffffffu, v, 1);
            v += __shfl_xor_sync(0xffffffffu, v, 2);
            v += __shfl_xor_sync(0xffffffffu, v, 4);
            if ((lane & 7) == 0) {
                int row = bm + (tid >> 3) + i * 32;
                if (row < M) ddOut[row] = v;
            }
        }
    }

    // ss: per-row dot of C with sv, reduced across quads + warps, atomic across bn
    if (tid < 128) ssred[tid] = 0.f;
    __syncthreads();
#pragma unroll
    for (int mt = 0; mt < 4; mt++) {
        float p0 = 0.f, p1 = 0.f;
#pragma unroll
        for (int nt = 0; nt < 4; nt++) {
            int col0 = bn + wn * 32 + nt * 8 + tg * 2;
            float2 sva = __ldg((const float2*)sv + (col0 >> 1));
            p0 += c[mt][nt][0] * sva.x + c[mt][nt][1] * sva.y;
            p1 += c[mt][nt][2] * sva.x + c[mt][nt][3] * sva.y;
        }
        p0 += __shfl_xor_sync(0xffffffffu, p0, 1);
        p0 += __shfl_xor_sync(0xffffffffu, p0, 2);
        p1 += __shfl_xor_sync(0xffffffffu, p1, 1);
        p1 += __shfl_xor_sync(0xffffffffu, p1, 2);
        if (tg == 0) {
            int rl = wm * 64 + mt * 16 + g;
            atomicAdd(&ssred[rl], p0);
            atomicAdd(&ssred[rl + 8], p1);
        }
    }
    __syncthreads();
    if (tid < 128) {
        int row = bm + tid;
        if (row < M) atomicAdd(ssOut + row, ssred[tid]);
    }

    // C store (fp16)
#pragma unroll
    for (int mt = 0; mt < 4; mt++) {
        int r0 = bm + wm * 64 + mt * 16 + g;
#pragma unroll
        for (int nt = 0; nt < 4; nt++) {
            int cc = bn + wn * 32 + nt * 8 + tg * 2;
            __half2 p0 = __floats2half2_rn(c[mt][nt][0], c[mt][nt][1]);
            __half2 p1 = __floats2half2_rn(c[mt][nt][2], c[mt][nt][3]);
            if (r0 < M)     *(__half2*)(C + (size_t)r0 * N + cc) = p0;
            if (r0 + 8 < M) *(__half2*)(C + (size_t)(r0 + 8) * N + cc) = p1;
        }
    }
}

// ---------------- small-N GEMM (layer 3): K=256, N=16, fused ss/dd ----------------
__global__ void __launch_bounds__(512) gemm_n16_kernel(const float* __restrict__ X,
                                                       const float* __restrict__ W,
                                                       float* __restrict__ H, int M,
                                                       const float* __restrict__ sv,
                                                       const float* __restrict__ dv,
                                                       float* __restrict__ ssOut,
                                                       float* __restrict__ ddOut) {
    __shared__ float Ws[256 * 16];
    __shared__ float Xs[32 * 256];
    int tid = threadIdx.x;
    int row0 = blockIdx.x * 32;
    for (int i = tid; i < 256 * 16 / 4; i += 512)
        *(float4*)&Ws[i * 4] = *(const float4*)(W + i * 4);
#pragma unroll
    for (int i = 0; i < 4; i++) {
        int lin = tid + i * 512;
        int r = lin / 64;
        int c4 = lin % 64;
        float4 v = make_float4(0.f, 0.f, 0.f, 0.f);
        if (row0 + r < M)
            v = *(const float4*)(X + (size_t)(row0 + r) * 256 + c4 * 4);
        *(float4*)&Xs[r * 256 + c4 * 4] = v;
    }
    __syncthreads();

    // dd: warp w handles rows w*2, w*2+1 (X row dot dv over K=256)
    {
        int w = tid >> 5, ln = tid & 31;
        float4 dva = __ldg((const float4*)dv + ln * 2);
        float4 dvb = __ldg((const float4*)dv + ln * 2 + 1);
#pragma unroll
        for (int rr = 0; rr < 2; rr++) {
            int r = w * 2 + rr;
            const float4* xr = (const float4*)(Xs + r * 256) + ln * 2;
            float4 a = xr[0], b = xr[1];
            float v = a.x * dva.x + a.y * dva.y + a.z * dva.z + a.w * dva.w
                    + b.x * dvb.x + b.y * dvb.y + b.z * dvb.z + b.w * dvb.w;
#pragma unroll
            for (int o = 16; o; o >>= 1) v += __shfl_xor_sync(0xffffffffu, v, o);
            if (ln == 0 && row0 + r < M) ddOut[row0 + r] = v;
        }
    }

    int r = tid / 16, c = tid % 16;
    float acc = 0.f;
#pragma unroll 8
    for (int k = 0; k < 256; k++) acc += Xs[r * 256 + k] * Ws[k * 16 + c];

    // ss: per-row dot of H row with sv (16 wide), half-warp reduce
    float sp = acc * __ldg(sv + c);
    sp += __shfl_xor_sync(0xffffffffu, sp, 1);
    sp += __shfl_xor_sync(0xffffffffu, sp, 2);
    sp += __shfl_xor_sync(0xffffffffu, sp, 4);
    sp += __shfl_xor_sync(0xffffffffu, sp, 8);
    if (row0 + r < M) {
        if ((tid & 15) == 0) ssOut[row0 + r] = sp;
        H[(size_t)(row0 + r) * 16 + c] = acc;
    }
}

// ---------------- fused dual W@a : dv = W@a for both directions ----------------
__global__ void wv2_kernel(const float* __restrict__ W0, const float* __restrict__ a0,
                           float* __restrict__ o0,
                           const float* __restrict__ W1, const float* __restrict__ a1,
                           float* __restrict__ o1, int Fin, int Fout) {
    const float* W = blockIdx.y ? W1 : W0;
    const float* a = blockIdx.y ? a1 : a0;
    float* o = blockIdx.y ? o1 : o0;
    int w = (blockIdx.x * blockDim.x + threadIdx.x) >> 5;
    int lane = threadIdx.x & 31;
    if (w >= Fin) return;
    float s = 0.f;
    for (int j = lane; j < Fout; j += 32) s += W[(size_t)w * Fout + j] * a[j];
    for (int o2 = 16; o2; o2 >>= 1) s += __shfl_down_sync(0xffffffffu, s, o2);
    if (lane == 0) o[w] = s;
}

// ---------------- concatenated 2-direction CSR build ----------------
__global__ void hist2_kernel(const int* __restrict__ eab, const int* __restrict__ eba,
                             int* __restrict__ cnt) {
    int e = blockIdx.x * blockDim.x + threadIdx.x;
    if (e < NEDGE) atomicAdd(&cnt[eab[NEDGE + e]], 1);
    else if (e < 2 * NEDGE) atomicAdd(&cnt[NB + eba[NEDGE + e - NEDGE]], 1);
}

__global__ void scan1_kernel(const int* __restrict__ cnt, int* __restrict__ rowptr,
                             int* __restrict__ bsum, int n) {
    __shared__ int sh[1024];
    int i = blockIdx.x * 1024 + threadIdx.x;
    int v = (i < n) ? cnt[i] : 0;
    sh[threadIdx.x] = v;
    __syncthreads();
    for (int off = 1; off < 1024; off <<= 1) {
        int t = (threadIdx.x >= off) ? sh[threadIdx.x - off] : 0;
        __syncthreads();
        sh[threadIdx.x] += t;
        __syncthreads();
    }
    if (i < n) rowptr[i + 1] = sh[threadIdx.x];
    if (threadIdx.x == 1023) bsum[blockIdx.x] = sh[1023];
}

__global__ void scan2_kernel(int* __restrict__ bsum, int nb) {
    __shared__ int sh[128];
    int t = threadIdx.x;
    int v = (t < nb) ? bsum[t] : 0;
    sh[t] = v;
    __syncthreads();
    for (int off = 1; off < 128; off <<= 1) {
        int u = (t >= off) ? sh[t - off] : 0;
        __syncthreads();
        sh[t] += u;
        __syncthreads();
    }
    if (t < nb) bsum[t] = sh[t] - v;  // exclusive
}

__global__ void scan3_kernel(int* __restrict__ rowptr, const int* __restrict__ bsum, int n) {
    int i = blockIdx.x * 1024 + threadIdx.x;
    if (i < n) rowptr[i + 1] += bsum[blockIdx.x];
    if (i == 0) rowptr[0] = 0;
}

__global__ void scatter2_kernel(const int* __restrict__ eab, const int* __restrict__ eba,
                                const int* __restrict__ rowptr, int* __restrict__ fill,
                                int* __restrict__ sorted) {
    int e = blockIdx.x * blockDim.x + threadIdx.x;
    int s, seg;
    if (e < NEDGE) { s = eab[e]; seg = eab[NEDGE + e]; }
    else if (e < 2 * NEDGE) { int e2 = e - NEDGE; s = eba[e2]; seg = NB + eba[NEDGE + e2]; }
    else return;
    int p = rowptr[seg] + atomicAdd(&fill[seg], 1);
    sorted[p] = s;
}

// ---------------- fused GAT aggregation, FOUT=256, fp16 H gather ----------------
__global__ void __launch_bounds__(256) gat256h_kernel(const int* __restrict__ rowptr,
                                                      const int* __restrict__ ssrc,
                                                      const float* __restrict__ ss,
                                                      const float* __restrict__ dd,
                                                      const __half* __restrict__ H,
                                                      const float* __restrict__ bias,
                                                      float* __restrict__ out,
                                                      int ndst, int doRelu) {
    int w = (blockIdx.x * blockDim.x + threadIdx.x) >> 5;
    int lane = threadIdx.x & 31;
    if (w >= ndst) return;
    int b0 = rowptr[w], b1 = rowptr[w + 1];
    float ddv = dd[w];

    float mx = __int_as_float(0xff800000);
    for (int i = b0 + lane; i < b1; i += 32) {
        float v = __ldg(ss + ssrc[i]) + ddv;
        v = v > 0.f ? v : 0.2f * v;
        mx = fmaxf(mx, v);
    }
#pragma unroll
    for (int o = 16; o; o >>= 1) mx = fmaxf(mx, __shfl_xor_sync(0xffffffffu, mx, o));

    float acc[8] = {};
    float sum = 0.f;
    for (int base = b0; base < b1; base += 32) {
        int i = base + lane;
        float wgt = 0.f;
        int s = 0;
        if (i < b1) {
            s = ssrc[i];
            float v = __ldg(ss + s) + ddv;
            v = v > 0.f ? v : 0.2f * v;
            wgt = __expf(v - mx);
        }
        sum += wgt;
        int nn = min(32, b1 - base);
        for (int t = 0; t < nn; t++) {
            float wt = __shfl_sync(0xffffffffu, wgt, t);
            int st = __shfl_sync(0xffffffffu, s, t);
            uint4 u = __ldg((const uint4*)(H + (size_t)st * 256) + lane);
            const __half2* hh = (const __half2*)&u;
#pragma unroll
            for (int j = 0; j < 4; j++) {
                float2 f = __half22float2(hh[j]);
                acc[2 * j]     += wt * f.x;
                acc[2 * j + 1] += wt * f.y;
            }
        }
    }
#pragma unroll
    for (int o = 16; o; o >>= 1) sum += __shfl_xor_sync(0xffffffffu, sum, o);
    float inv = 1.f / (sum + 1e-16f);

    float4 bb0 = __ldg((const float4*)bias + lane * 2);
    float4 bb1 = __ldg((const float4*)bias + lane * 2 + 1);
    float4 o0, o1;
    o0.x = acc[0] * inv + bb0.x; o0.y = acc[1] * inv + bb0.y;
    o0.z = acc[2] * inv + bb0.z; o0.w = acc[3] * inv + bb0.w;
    o1.x = acc[4] * inv + bb1.x; o1.y = acc[5] * inv + bb1.y;
    o1.z = acc[6] * inv + bb1.z; o1.w = acc[7] * inv + bb1.w;
    if (doRelu) {
        o0.x = fmaxf(o0.x, 0.f); o0.y = fmaxf(o0.y, 0.f);
        o0.z = fmaxf(o0.z, 0.f); o0.w = fmaxf(o0.w, 0.f);
        o1.x = fmaxf(o1.x, 0.f); o1.y = fmaxf(o1.y, 0.f);
        o1.z = fmaxf(o1.z, 0.f); o1.w = fmaxf(o1.w, 0.f);
    }
    float4* orow = (float4*)(out + (size_t)w * 256);
    orow[lane * 2]     = o0;
    orow[lane * 2 + 1] = o1;
}

// ---------------- fused GAT aggregation, FOUT=16, half-warp per edge ----------------
__global__ void __launch_bounds__(256) gat16_kernel(const int* __restrict__ rowptr,
                                                    const int* __restrict__ ssrc,
                                                    const float* __restrict__ ss,
                                                    const float* __restrict__ dd,
                                                    const float* __restrict__ H,
                                                    const float* __restrict__ bias,
                                                    float* __restrict__ out, int ndst) {
    int w = (blockIdx.x * blockDim.x + threadIdx.x) >> 5;
    int lane = threadIdx.x & 31;
    if (w >= ndst) return;
    int b0 = rowptr[w], b1 = rowptr[w + 1];
    float ddv = dd[w];
    int half = lane >> 4, fl = lane & 15;

    float mx = __int_as_float(0xff800000);
    for (int i = b0 + lane; i < b1; i += 32) {
        float v = __ldg(ss + ssrc[i]) + ddv;
        v = v > 0.f ? v : 0.2f * v;
        mx = fmaxf(mx, v);
    }
#pragma unroll
    for (int o = 16; o; o >>= 1) mx = fmaxf(mx, __shfl_xor_sync(0xffffffffu, mx, o));

    float acc = 0.f;
    float sum = 0.f;
    for (int base = b0; base < b1; base += 32) {
        int i = base + lane;
        float wgt = 0.f;
        int s = 0;
        if (i < b1) {
            s = ssrc[i];
            float v = __ldg(ss + s) + ddv;
            v = v > 0.f ? v : 0.2f * v;
            wgt = __expf(v - mx);
        }
        sum += wgt;
        int nn = min(32, b1 - base);
        for (int t = 0; t < nn; t += 2) {
            int tt = t + half;
            float wt = __shfl_sync(0xffffffffu, wgt, tt);
            int st = __shfl_sync(0xffffffffu, s, tt);
            if (tt < nn) acc += wt * __ldg(H + (size_t)st * 16 + fl);
        }
    }
#pragma unroll
    for (int o = 16; o; o >>= 1) sum += __shfl_xor_sync(0xffffffffu, sum, o);
    acc += __shfl_xor_sync(0xffffffffu, acc, 16);
    float inv = 1.f / (sum + 1e-16f);
    if (lane < 16)
        out[(size_t)w * 16 + lane] = acc * inv + __ldg(bias + lane);
}

// ---------------- readout ----------------
__global__ void sumrows16_kernel(const float* __restrict__ xb, const int* __restrict__ dstidx,
                                 float* __restrict__ out16, int L) {
    __shared__ float sh[16];
    if (threadIdx.x < 16) sh[threadIdx.x] = 0.f;
    __syncthreads();
    float loc[16];
#pragma unroll
    for (int k = 0; k < 16; k++) loc[k] = 0.f;
    for (int t = blockIdx.x * blockDim.x + threadIdx.x; t < L; t += gridDim.x * blockDim.x) {
        const float* row = xb + (size_t)dstidx[t] * 16;
#pragma unroll
        for (int k = 0; k < 16; k++) loc[k] += row[k];
    }
#pragma unroll
    for (int k = 0; k < 16; k++) atomicAdd(&sh[k], loc[k]);
    __syncthreads();
    if (threadIdx.x < 16) atomicAdd(&out16[threadIdx.x], sh[threadIdx.x]);
}

__global__ void pred_kernel(const float* __restrict__ xa, const int* __restrict__ srcidx,
                            const float* __restrict__ sum16, float* __restrict__ pred, int L) {
    int t = blockIdx.x * blockDim.x + threadIdx.x;
    if (t >= L) return;
    const float* row = xa + (size_t)srcidx[t] * 16;
    float s = 0.f;
#pragma unroll
    for (int k = 0; k < 16; k++) s += row[k] * __ldg(sum16 + k);
    pred[t] = s;
}

// ---------------- host orchestration ----------------
static inline int cdiv(int a, int b) { return (a + b - 1) / b; }

extern "C" void kernel_launch(void* const* d_in, const int* in_sizes, int n_in,
                              void* d_out, int out_size) {
    const float* xAin = (const float*)d_in[0];
    const float* xBin = (const float*)d_in[1];
    const int* ei_ab = (const int*)d_in[2];
    const int* ei_ba = (const int*)d_in[3];
    const int* srcI = (const int*)d_in[4];
    const int* dstI = (const int*)d_in[5];

    const float* Wab[3]  = {(const float*)d_in[6],  (const float*)d_in[14], (const float*)d_in[22]};
    const float* asab[3] = {(const float*)d_in[7],  (const float*)d_in[15], (const float*)d_in[23]};
    const float* adab[3] = {(const float*)d_in[8],  (const float*)d_in[16], (const float*)d_in[24]};
    const float* bab[3]  = {(const float*)d_in[9],  (const float*)d_in[17], (const float*)d_in[25]};
    const float* Wba[3]  = {(const float*)d_in[10], (const float*)d_in[18], (const float*)d_in[26]};
    const float* asba[3] = {(const float*)d_in[11], (const float*)d_in[19], (const float*)d_in[27]};
    const float* adba[3] = {(const float*)d_in[12], (const float*)d_in[20], (const float*)d_in[28]};
    const float* bba[3]  = {(const float*)d_in[13], (const float*)d_in[21], (const float*)d_in[29]};

    float* out = (float*)d_out;
    float* pred = out;
    float* xaOut = out + LPRED;
    float* xbOut = xaOut + (size_t)NA * 16;

    float* F = nullptr;
    int* I = nullptr;
    cudaGetSymbolAddress((void**)&F, g_fpool);
    cudaGetSymbolAddress((void**)&I, g_ipool);

    float* XA = F + OFF_XA;
    float* XB = F + OFF_XB;
    float* HABf = F + OFF_HAB;
    float* HBAf = F + OFF_HBA;
    __half* HABh = (__half*)(F + OFF_HAB);
    __half* HBAh = (__half*)(F + OFF_HBA);
    float* SSAB = F + OFF_SSAB;
    float* DDAB = F + OFF_DDAB;
    float* SSBA = F + OFF_SSBA;
    float* DDBA = F + OFF_DDBA;
    float* SV = F + OFF_SV;
    float* SUM16 = F + OFF_SUM16;
    float* WTAB = F + OFF_WTAB;
    float* WTBA = F + OFF_WTBA;

    int* RP2 = I + IOFF_RP2;
    int* CNT2 = I + IOFF_CNT2;
    int* FILL2 = I + IOFF_FILL2;
    int* SRT = I + IOFF_SRT;
    int* BSUM = I + IOFF_BSUM;

    // ---- concatenated CSR build (both directions in one pass) ----
    const int NSEG = NA + NB;                 // 100000
    const int nScanBlk = cdiv(NSEG, 1024);    // 98
    cudaMemsetAsync(CNT2, 0, NSEG * sizeof(int), 0);
    hist2_kernel<<<cdiv(2 * NEDGE, 256), 256>>>(ei_ab, ei_ba, CNT2);
    scan1_kernel<<<nScanBlk, 1024>>>(CNT2, RP2, BSUM, NSEG);
    scan2_kernel<<<1, 128>>>(BSUM, nScanBlk);
    scan3_kernel<<<nScanBlk, 1024>>>(RP2, BSUM, NSEG);
    cudaMemsetAsync(FILL2, 0, NSEG * sizeof(int), 0);
    scatter2_kernel<<<cdiv(2 * NEDGE, 256), 256>>>(ei_ab, ei_ba, RP2, FILL2, SRT);

    const int FinL[3] = {128, 256, 256};
    const int FoutL[3] = {256, 256, 16};

    for (int l = 0; l < 3; l++) {
        const float* xa = (l == 0) ? xAin : XA;
        const float* xb = (l == 0) ? xBin : XB;
        int Fin = FinL[l], Fout = FoutL[l];

        // zero ss accumulators (SSAB..DDBA are contiguous: 4*50000 floats)
        cudaMemsetAsync(SSAB, 0, 4 * NA * sizeof(float), 0);

        // dv projections: SV+0 = Wab@adab, SV+256 = Wba@adba
        wv2_kernel<<<dim3(cdiv(Fin, 8), 2), 256>>>(Wab[l], adab[l], SV + 0,
                                                   Wba[l], adba[l], SV + 256, Fin, Fout);

        if (l < 2) {
            transpose2_kernel<<<dim3(256 / 32, Fin / 32, 2), dim3(32, 8)>>>(
                Wab[l], WTAB, Wba[l], WTBA, Fin, 256);
            // GEMM_ab: A=xa -> HAB, ss_ab (C . asab), dd_ba (A . (Wba@adba))
            gemm_f16x3_kernel<<<dim3(cdiv(NA, 128), 2), 256>>>(
                xa, WTAB, HABh, NA, 256, Fin, asab[l], SV + 256, SSAB, DDBA);
            // GEMM_ba: A=xb -> HBA, ss_ba (C . asba), dd_ab (A . (Wab@adab))
            gemm_f16x3_kernel<<<dim3(cdiv(NB, 128), 2), 256>>>(
                xb, WTBA, HBAh, NB, 256, Fin, asba[l], SV + 0, SSBA, DDAB);

            gat256h_kernel<<<cdiv(NB, 8), 256>>>(RP2, SRT, SSAB, DDAB, HABh, bab[l], XB, NB, 1);
            gat256h_kernel<<<cdiv(NA, 8), 256>>>(RP2 + NB, SRT, SSBA, DDBA, HBAh, bba[l], XA, NA, 1);
        } else {
            gemm_n16_kernel<<<cdiv(NA, 32), 512>>>(xa, Wab[l], HABf, NA,
                                                   asab[l], SV + 256, SSAB, DDBA);
            gemm_n16_kernel<<<cdiv(NB, 32), 512>>>(xb, Wba[l], HBAf, NB,
                                                   asba[l], SV + 0, SSBA, DDAB);

            gat16_kernel<<<cdiv(NB, 8), 256>>>(RP2, SRT, SSAB, DDAB, HABf, bab[l], xbOut, NB);
            gat16_kernel<<<cdiv(NA, 8), 256>>>(RP2 + NB, SRT, SSBA, DDBA, HBAf, bba[l], xaOut, NA);
        }
    }

    // ---- readout ----
    cudaMemsetAsync(SUM16, 0, 16 * sizeof(float), 0);
    sumrows16_kernel<<<256, 256>>>(xbOut, dstI, SUM16, LPRED);
    pred_kernel<<<cdiv(LPRED, 256), 256>>>(xaOut, srcI, SUM16, pred, LPRED);
}

// round 7
// speedup vs baseline: 1.7399x; 1.0965x over previous
#include <cuda_runtime.h>
#include <cuda_fp16.h>
#include <math.h>

#define NA 50000
#define NB 50000
#define NEDGE 1000000
#define LPRED 100000

// ---------------- device scratch pools ----------------
// fp16 split X buffers (halves stored in float pool; counts below in floats)
#define OFF_XAH   0u                    // 50000*256 halves = 6.4M floats
#define OFF_XAL   6400000u
#define OFF_XBH   12800000u
#define OFF_XBL   19200000u
#define OFF_HAB   25600000u             // 12.8M floats (fp16 layers 1-2 / fp32 layer 3)
#define OFF_HBA   38400000u
#define OFF_SSAB  51200000u             // NA
#define OFF_SSBA  51250000u             // NB  (ss pair contiguous for one memset)
#define OFF_DDAB  51300000u             // NB
#define OFF_DDBA  51350000u             // NA
#define OFF_SV    51400000u             // 6*256 dv vectors (padded 2048)
#define OFF_SUM16 51402048u             // 16
#define OFF_WTABH 51402064u             // 256*256 halves = 32768 floats
#define OFF_WTABL 51434832u
#define OFF_WTBAH 51467600u
#define OFF_WTBAL 51500368u
#define FPOOL_N   51533136u

#define IOFF_RP2   0u                   // 100001
#define IOFF_CNT2  100001u              // 100000
#define IOFF_FILL2 200001u              // 100000
#define IOFF_SRT   300001u              // 2*NEDGE
#define IOFF_BSUM  2300001u             // 128
#define IPOOL_N    2300129u

static __device__ float g_fpool[FPOOL_N];
static __device__ int   g_ipool[IPOOL_N];

// ---------------- fp16 hi/lo split via bit truncation ----------------
__device__ __forceinline__ void split2(float x, float y, __half2* ph, __half2* pl) {
    float hx = __uint_as_float(__float_as_uint(x) & 0xFFFFE000u);
    float hy = __uint_as_float(__float_as_uint(y) & 0xFFFFE000u);
    *ph = __halves2half2(__float2half_rn(hx), __float2half_rn(hy));
    *pl = __halves2half2(__float2half_rn(x - hx), __float2half_rn(y - hy));
}

__device__ __forceinline__ void split_store4(float4 v, __half* ph, __half* pl) {
    __half2 h01, l01, h23, l23;
    split2(v.x, v.y, &h01, &l01);
    split2(v.z, v.w, &h23, &l23);
    *(__half2*)(ph)     = h01;
    *(__half2*)(ph + 2) = h23;
    *(__half2*)(pl)     = l01;
    *(__half2*)(pl + 2) = l23;
}

#define MMA_F16(cc, aa, bb)                                                         \
    asm volatile(                                                                   \
        "mma.sync.aligned.m16n8k16.row.col.f32.f16.f16.f32 "                        \
        "{%0,%1,%2,%3},{%4,%5,%6,%7},{%8,%9},{%0,%1,%2,%3};\n"                      \
        : "+f"((cc)[0]), "+f"((cc)[1]), "+f"((cc)[2]), "+f"((cc)[3])                \
        : "r"((aa)[0]), "r"((aa)[1]), "r"((aa)[2]), "r"((aa)[3]),                   \
          "r"((bb)[0]), "r"((bb)[1]))

// ---------------- transpose + split: Wt{h,l}[N][K] = split(W[K][N]) ----------------
__global__ void transpose2split_kernel(const float* __restrict__ W0,
                                       __half* __restrict__ T0h, __half* __restrict__ T0l,
                                       const float* __restrict__ W1,
                                       __half* __restrict__ T1h, __half* __restrict__ T1l,
                                       int K, int N) {
    __shared__ float t[32][33];
    const float* W = blockIdx.z ? W1 : W0;
    __half* Th = blockIdx.z ? T1h : T0h;
    __half* Tl = blockIdx.z ? T1l : T0l;
    int n0 = blockIdx.x * 32, k0 = blockIdx.y * 32;
#pragma unroll
    for (int i = 0; i < 4; i++) {
        int k = k0 + threadIdx.y + i * 8;
        t[threadIdx.y + i * 8][threadIdx.x] = W[(size_t)k * N + n0 + threadIdx.x];
    }
    __syncthreads();
#pragma unroll
    for (int i = 0; i < 4; i++) {
        int n = n0 + threadIdx.y + i * 8;
        float v = t[threadIdx.x][threadIdx.y + i * 8];
        float hv = __uint_as_float(__float_as_uint(v) & 0xFFFFE000u);
        Th[(size_t)n * K + k0 + threadIdx.x] = __float2half_rn(hv);
        Tl[(size_t)n * K + k0 + threadIdx.x] = __float2half_rn(v - hv);
    }
}

// ---------------- layer-1 X split (K=128) + dd dot ----------------
__global__ void splitX_kernel(const float* __restrict__ X,
                              __half* __restrict__ Xh, __half* __restrict__ Xl,
                              const float* __restrict__ dv, float* __restrict__ dd,
                              int M) {
    int w = (blockIdx.x * blockDim.x + threadIdx.x) >> 5;
    int lane = threadIdx.x & 31;
    if (w >= M) return;
    float4 v = *(const float4*)(X + (size_t)w * 128 + lane * 4);
    float4 dvv = __ldg((const float4*)dv + lane);
    float acc = v.x * dvv.x + v.y * dvv.y + v.z * dvv.z + v.w * dvv.w;
    split_store4(v, Xh + (size_t)w * 128 + lane * 4, Xl + (size_t)w * 128 + lane * 4);
#pragma unroll
    for (int o = 16; o; o >>= 1) acc += __shfl_xor_sync(0xffffffffu, acc, o);
    if (lane == 0) dd[w] = acc;
}

// ---------------- tensor-core GEMM, pre-split operands ----------------
// C(half)[M,N] = A[M,K] @ Bt[N,K]^T (3-term fp16 hi/lo emulation)
// plus ssOut[r] += sum_c C[r,c]*sv[c]
__global__ void __launch_bounds__(256) gemm_f16x3_kernel(const __half* __restrict__ Ahg,
                                                         const __half* __restrict__ Alg,
                                                         const __half* __restrict__ Bhg,
                                                         const __half* __restrict__ Blg,
                                                         __half* __restrict__ C,
                                                         int M, int N, int K,
                                                         const float* __restrict__ sv,
                                                         float* __restrict__ ssOut) {
    __shared__ __half Ah[128][40], Al[128][40], Bh[128][40], Bl[128][40];
    __shared__ float ssred[128];
    int tid = threadIdx.x;
    int warp = tid >> 5, lane = tid & 31;
    int g = lane >> 2, tg = lane & 3;
    int wm = warp >> 2, wn = warp & 3;
    int bm = blockIdx.x * 128, bn = blockIdx.y * 128;

    float c[4][4][4] = {};

    for (int k0 = 0; k0 < K; k0 += 32) {
        // stage (pure copy): 512 uint4 per array, 2 per thread per array
#pragma unroll
        for (int j = 0; j < 2; j++) {
            int idx = tid + j * 256;
            int row = idx >> 2, q = (idx & 3) * 8;   // halves offset within 32-k tile
            uint4 vh = make_uint4(0, 0, 0, 0), vl = make_uint4(0, 0, 0, 0);
            int gr = bm + row;
            if (gr < M) {
                vh = *(const uint4*)(Ahg + (size_t)gr * K + k0 + q);
                vl = *(const uint4*)(Alg + (size_t)gr * K + k0 + q);
            }
            *(uint4*)&Ah[row][q] = vh;
            *(uint4*)&Al[row][q] = vl;
            uint4 wh = *(const uint4*)(Bhg + (size_t)(bn + row) * K + k0 + q);
            uint4 wl = *(const uint4*)(Blg + (size_t)(bn + row) * K + k0 + q);
            *(uint4*)&Bh[row][q] = wh;
            *(uint4*)&Bl[row][q] = wl;
        }
        __syncthreads();

#pragma unroll
        for (int ks = 0; ks < 2; ks++) {
            int kc = ks * 16 + tg * 2;
            unsigned ah[4][4], al[4][4], bh[4][2], bl[4][2];
#pragma unroll
            for (int mt = 0; mt < 4; mt++) {
                int r = wm * 64 + mt * 16 + g;
                ah[mt][0] = *(const unsigned*)&Ah[r][kc];
                ah[mt][1] = *(const unsigned*)&Ah[r + 8][kc];
                ah[mt][2] = *(const unsigned*)&Ah[r][kc + 8];
                ah[mt][3] = *(const unsigned*)&Ah[r + 8][kc + 8];
                al[mt][0] = *(const unsigned*)&Al[r][kc];
                al[mt][1] = *(const unsigned*)&Al[r + 8][kc];
                al[mt][2] = *(const unsigned*)&Al[r][kc + 8];
                al[mt][3] = *(const unsigned*)&Al[r + 8][kc + 8];
            }
#pragma unroll
            for (int nt = 0; nt < 4; nt++) {
                int n = wn * 32 + nt * 8 + g;
                bh[nt][0] = *(const unsigned*)&Bh[n][kc];
                bh[nt][1] = *(const unsigned*)&Bh[n][kc + 8];
                bl[nt][0] = *(const unsigned*)&Bl[n][kc];
                bl[nt][1] = *(const unsigned*)&Bl[n][kc + 8];
            }
#pragma unroll
            for (int mt = 0; mt < 4; mt++)
#pragma unroll
                for (int nt = 0; nt < 4; nt++) {
                    MMA_F16(c[mt][nt], ah[mt], bl[nt]);
                    MMA_F16(c[mt][nt], al[mt], bh[nt]);
                    MMA_F16(c[mt][nt], ah[mt], bh[nt]);
                }
        }
        __syncthreads();
    }

    // ss: per-row dot of C with sv
    if (tid < 128) ssred[tid] = 0.f;
    __syncthreads();
#pragma unroll
    for (int mt = 0; mt < 4; mt++) {
        float p0 = 0.f, p1 = 0.f;
#pragma unroll
        for (int nt = 0; nt < 4; nt++) {
            int col0 = bn + wn * 32 + nt * 8 + tg * 2;
            float2 sva = __ldg((const float2*)sv + (col0 >> 1));
            p0 += c[mt][nt][0] * sva.x + c[mt][nt][1] * sva.y;
            p1 += c[mt][nt][2] * sva.x + c[mt][nt][3] * sva.y;
        }
        p0 += __shfl_xor_sync(0xffffffffu, p0, 1);
        p0 += __shfl_xor_sync(0xffffffffu, p0, 2);
        p1 += __shfl_xor_sync(0xffffffffu, p1, 1);
        p1 += __shfl_xor_sync(0xffffffffu, p1, 2);
        if (tg == 0) {
            int rl = wm * 64 + mt * 16 + g;
            atomicAdd(&ssred[rl], p0);
            atomicAdd(&ssred[rl + 8], p1);
        }
    }
    __syncthreads();
    if (tid < 128) {
        int row = bm + tid;
        if (row < M) atomicAdd(ssOut + row, ssred[tid]);
    }

    // C store (fp16)
#pragma unroll
    for (int mt = 0; mt < 4; mt++) {
        int r0 = bm + wm * 64 + mt * 16 + g;
#pragma unroll
        for (int nt = 0; nt < 4; nt++) {
            int cc = bn + wn * 32 + nt * 8 + tg * 2;
            __half2 p0 = __floats2half2_rn(c[mt][nt][0], c[mt][nt][1]);
            __half2 p1 = __floats2half2_rn(c[mt][nt][2], c[mt][nt][3]);
            if (r0 < M)     *(__half2*)(C + (size_t)r0 * N + cc) = p0;
            if (r0 + 8 < M) *(__half2*)(C + (size_t)(r0 + 8) * N + cc) = p1;
        }
    }
}

// ---------------- small-N GEMM (layer 3): X from hi+lo halves, fused ss ----------------
__global__ void __launch_bounds__(512) gemm_n16_kernel(const __half* __restrict__ Xh,
                                                       const __half* __restrict__ Xl,
                                                       const float* __restrict__ W,
                                                       float* __restrict__ H, int M,
                                                       const float* __restrict__ sv,
                                                       float* __restrict__ ssOut) {
    __shared__ float Ws[256 * 16];
    __shared__ float Xs[32 * 256];
    int tid = threadIdx.x;
    int row0 = blockIdx.x * 32;
    for (int i = tid; i < 256 * 16 / 4; i += 512)
        *(float4*)&Ws[i * 4] = *(const float4*)(W + i * 4);
#pragma unroll
    for (int i = 0; i < 4; i++) {
        int lin = tid + i * 512;
        int r = lin / 64;
        int c4 = lin % 64;
        float4 v = make_float4(0.f, 0.f, 0.f, 0.f);
        if (row0 + r < M) {
            uint2 vh = *(const uint2*)(Xh + (size_t)(row0 + r) * 256 + c4 * 4);
            uint2 vl = *(const uint2*)(Xl + (size_t)(row0 + r) * 256 + c4 * 4);
            const __half2* ph = (const __half2*)&vh;
            const __half2* pl = (const __half2*)&vl;
            float2 a0 = __half22float2(ph[0]), a1 = __half22float2(ph[1]);
            float2 b0 = __half22float2(pl[0]), b1 = __half22float2(pl[1]);
            v = make_float4(a0.x + b0.x, a0.y + b0.y, a1.x + b1.x, a1.y + b1.y);
        }
        *(float4*)&Xs[r * 256 + c4 * 4] = v;
    }
    __syncthreads();

    int r = tid / 16, c = tid % 16;
    float acc = 0.f;
#pragma unroll 8
    for (int k = 0; k < 256; k++) acc += Xs[r * 256 + k] * Ws[k * 16 + c];

    float sp = acc * __ldg(sv + c);
    sp += __shfl_xor_sync(0xffffffffu, sp, 1);
    sp += __shfl_xor_sync(0xffffffffu, sp, 2);
    sp += __shfl_xor_sync(0xffffffffu, sp, 4);
    sp += __shfl_xor_sync(0xffffffffu, sp, 8);
    if (row0 + r < M) {
        if ((tid & 15) == 0) ssOut[row0 + r] = sp;
        H[(size_t)(row0 + r) * 16 + c] = acc;
    }
}

// ---------------- fused dual W@a ----------------
__global__ void wv2_kernel(const float* __restrict__ W0, const float* __restrict__ a0,
                           float* __restrict__ o0,
                           const float* __restrict__ W1, const float* __restrict__ a1,
                           float* __restrict__ o1, int Fin, int Fout) {
    const float* W = blockIdx.y ? W1 : W0;
    const float* a = blockIdx.y ? a1 : a0;
    float* o = blockIdx.y ? o1 : o0;
    int w = (blockIdx.x * blockDim.x + threadIdx.x) >> 5;
    int lane = threadIdx.x & 31;
    if (w >= Fin) return;
    float s = 0.f;
    for (int j = lane; j < Fout; j += 32) s += W[(size_t)w * Fout + j] * a[j];
    for (int o2 = 16; o2; o2 >>= 1) s += __shfl_down_sync(0xffffffffu, s, o2);
    if (lane == 0) o[w] = s;
}

// ---------------- concatenated 2-direction CSR build ----------------
__global__ void hist2_kernel(const int* __restrict__ eab, const int* __restrict__ eba,
                             int* __restrict__ cnt) {
    int e = blockIdx.x * blockDim.x + threadIdx.x;
    if (e < NEDGE) atomicAdd(&cnt[eab[NEDGE + e]], 1);
    else if (e < 2 * NEDGE) atomicAdd(&cnt[NB + eba[NEDGE + e - NEDGE]], 1);
}

__global__ void scan1_kernel(const int* __restrict__ cnt, int* __restrict__ rowptr,
                             int* __restrict__ bsum, int n) {
    __shared__ int sh[1024];
    int i = blockIdx.x * 1024 + threadIdx.x;
    int v = (i < n) ? cnt[i] : 0;
    sh[threadIdx.x] = v;
    __syncthreads();
    for (int off = 1; off < 1024; off <<= 1) {
        int t = (threadIdx.x >= off) ? sh[threadIdx.x - off] : 0;
        __syncthreads();
        sh[threadIdx.x] += t;
        __syncthreads();
    }
    if (i < n) rowptr[i + 1] = sh[threadIdx.x];
    if (threadIdx.x == 1023) bsum[blockIdx.x] = sh[1023];
}

__global__ void scan2_kernel(int* __restrict__ bsum, int nb) {
    __shared__ int sh[128];
    int t = threadIdx.x;
    int v = (t < nb) ? bsum[t] : 0;
    sh[t] = v;
    __syncthreads();
    for (int off = 1; off < 128; off <<= 1) {
        int u = (t >= off) ? sh[t - off] : 0;
        __syncthreads();
        sh[t] += u;
        __syncthreads();
    }
    if (t < nb) bsum[t] = sh[t] - v;
}

__global__ void scan3_kernel(int* __restrict__ rowptr, const int* __restrict__ bsum, int n) {
    int i = blockIdx.x * 1024 + threadIdx.x;
    if (i < n) rowptr[i + 1] += bsum[blockIdx.x];
    if (i == 0) rowptr[0] = 0;
}

__global__ void scatter2_kernel(const int* __restrict__ eab, const int* __restrict__ eba,
                                const int* __restrict__ rowptr, int* __restrict__ fill,
                                int* __restrict__ sorted) {
    int e = blockIdx.x * blockDim.x + threadIdx.x;
    int s, seg;
    if (e < NEDGE) { s = eab[e]; seg = eab[NEDGE + e]; }
    else if (e < 2 * NEDGE) { int e2 = e - NEDGE; s = eba[e2]; seg = NB + eba[NEDGE + e2]; }
    else return;
    int p = rowptr[seg] + atomicAdd(&fill[seg], 1);
    sorted[p] = s;
}

// ---------------- fused GAT (FOUT=256): fp16 gather; writes split X + next dd ----------------
__global__ void __launch_bounds__(256) gat256h_kernel(const int* __restrict__ rowptr,
                                                      const int* __restrict__ ssrc,
                                                      const float* __restrict__ ss,
                                                      const float* __restrict__ dd,
                                                      const __half* __restrict__ H,
                                                      const float* __restrict__ bias,
                                                      __half* __restrict__ Xh,
                                                      __half* __restrict__ Xl,
                                                      const float* __restrict__ dvn,
                                                      float* __restrict__ ddn,
                                                      int ndst) {
    int w = (blockIdx.x * blockDim.x + threadIdx.x) >> 5;
    int lane = threadIdx.x & 31;
    if (w >= ndst) return;
    int b0 = rowptr[w], b1 = rowptr[w + 1];
    float ddv = dd[w];

    float mx = __int_as_float(0xff800000);
    for (int i = b0 + lane; i < b1; i += 32) {
        float v = __ldg(ss + ssrc[i]) + ddv;
        v = v > 0.f ? v : 0.2f * v;
        mx = fmaxf(mx, v);
    }
#pragma unroll
    for (int o = 16; o; o >>= 1) mx = fmaxf(mx, __shfl_xor_sync(0xffffffffu, mx, o));

    float acc[8] = {};
    float sum = 0.f;
    for (int base = b0; base < b1; base += 32) {
        int i = base + lane;
        float wgt = 0.f;
        int s = 0;
        if (i < b1) {
            s = ssrc[i];
            float v = __ldg(ss + s) + ddv;
            v = v > 0.f ? v : 0.2f * v;
            wgt = __expf(v - mx);
        }
        sum += wgt;
        int nn = min(32, b1 - base);
        for (int t = 0; t < nn; t++) {
            float wt = __shfl_sync(0xffffffffu, wgt, t);
            int st = __shfl_sync(0xffffffffu, s, t);
            uint4 u = __ldg((const uint4*)(H + (size_t)st * 256) + lane);
            const __half2* hh = (const __half2*)&u;
#pragma unroll
            for (int j = 0; j < 4; j++) {
                float2 f = __half22float2(hh[j]);
                acc[2 * j]     += wt * f.x;
                acc[2 * j + 1] += wt * f.y;
            }
        }
    }
#pragma unroll
    for (int o = 16; o; o >>= 1) sum += __shfl_xor_sync(0xffffffffu, sum, o);
    float inv = 1.f / (sum + 1e-16f);

    float4 bb0 = __ldg((const float4*)bias + lane * 2);
    float4 bb1 = __ldg((const float4*)bias + lane * 2 + 1);
    float4 o0, o1;
    o0.x = fmaxf(acc[0] * inv + bb0.x, 0.f); o0.y = fmaxf(acc[1] * inv + bb0.y, 0.f);
    o0.z = fmaxf(acc[2] * inv + bb0.z, 0.f); o0.w = fmaxf(acc[3] * inv + bb0.w, 0.f);
    o1.x = fmaxf(acc[4] * inv + bb1.x, 0.f); o1.y = fmaxf(acc[5] * inv + bb1.y, 0.f);
    o1.z = fmaxf(acc[6] * inv + bb1.z, 0.f); o1.w = fmaxf(acc[7] * inv + bb1.w, 0.f);

    // split store (hi/lo halves) for the next layer's GEMM
    union U4 { __half2 h2[4]; uint4 u; };
    U4 uh, ul;
    split2(o0.x, o0.y, &uh.h2[0], &ul.h2[0]);
    split2(o0.z, o0.w, &uh.h2[1], &ul.h2[1]);
    split2(o1.x, o1.y, &uh.h2[2], &ul.h2[2]);
    split2(o1.z, o1.w, &uh.h2[3], &ul.h2[3]);
    *(uint4*)(Xh + (size_t)w * 256 + lane * 8) = uh.u;
    *(uint4*)(Xl + (size_t)w * 256 + lane * 8) = ul.u;

    // next-layer dd = out . dvn
    float4 dva = __ldg((const float4*)dvn + lane * 2);
    float4 dvb = __ldg((const float4*)dvn + lane * 2 + 1);
    float dq = o0.x * dva.x + o0.y * dva.y + o0.z * dva.z + o0.w * dva.w
             + o1.x * dvb.x + o1.y * dvb.y + o1.z * dvb.z + o1.w * dvb.w;
#pragma unroll
    for (int o = 16; o; o >>= 1) dq += __shfl_xor_sync(0xffffffffu, dq, o);
    if (lane == 0) ddn[w] = dq;
}

// ---------------- fused GAT (FOUT=16, final layer, fp32 H) ----------------
__global__ void __launch_bounds__(256) gat16_kernel(const int* __restrict__ rowptr,
                                                    const int* __restrict__ ssrc,
                                                    const float* __restrict__ ss,
                                                    const float* __restrict__ dd,
                                                    const float* __restrict__ H,
                                                    const float* __restrict__ bias,
                                                    float* __restrict__ out, int ndst) {
    int w = (blockIdx.x * blockDim.x + threadIdx.x) >> 5;
    int lane = threadIdx.x & 31;
    if (w >= ndst) return;
    int b0 = rowptr[w], b1 = rowptr[w + 1];
    float ddv = dd[w];
    int half = lane >> 4, fl = lane & 15;

    float mx = __int_as_float(0xff800000);
    for (int i = b0 + lane; i < b1; i += 32) {
        float v = __ldg(ss + ssrc[i]) + ddv;
        v = v > 0.f ? v : 0.2f * v;
        mx = fmaxf(mx, v);
    }
#pragma unroll
    for (int o = 16; o; o >>= 1) mx = fmaxf(mx, __shfl_xor_sync(0xffffffffu, mx, o));

    float acc = 0.f;
    float sum = 0.f;
    for (int base = b0; base < b1; base += 32) {
        int i = base + lane;
        float wgt = 0.f;
        int s = 0;
        if (i < b1) {
            s = ssrc[i];
            float v = __ldg(ss + s) + ddv;
            v = v > 0.f ? v : 0.2f * v;
            wgt = __expf(v - mx);
        }
        sum += wgt;
        int nn = min(32, b1 - base);
        for (int t = 0; t < nn; t += 2) {
            int tt = t + half;
            float wt = __shfl_sync(0xffffffffu, wgt, tt);
            int st = __shfl_sync(0xffffffffu, s, tt);
            if (tt < nn) acc += wt * __ldg(H + (size_t)st * 16 + fl);
        }
    }
#pragma unroll
    for (int o = 16; o; o >>= 1) sum += __shfl_xor_sync(0xffffffffu, sum, o);
    acc += __shfl_xor_sync(0xffffffffu, acc, 16);
    float inv = 1.f / (sum + 1e-16f);
    if (lane < 16)
        out[(size_t)w * 16 + lane] = acc * inv + __ldg(bias + lane);
}

// ---------------- readout ----------------
__global__ void sumrows16_kernel(const float* __restrict__ xb, const int* __restrict__ dstidx,
                                 float* __restrict__ out16, int L) {
    __shared__ float sh[16];
    if (threadIdx.x < 16) sh[threadIdx.x] = 0.f;
    __syncthreads();
    float loc[16];
#pragma unroll
    for (int k = 0; k < 16; k++) loc[k] = 0.f;
    for (int t = blockIdx.x * blockDim.x + threadIdx.x; t < L; t += gridDim.x * blockDim.x) {
        const float* row = xb + (size_t)dstidx[t] * 16;
#pragma unroll
        for (int k = 0; k < 16; k++) loc[k] += row[k];
    }
#pragma unroll
    for (int k = 0; k < 16; k++) atomicAdd(&sh[k], loc[k]);
    __syncthreads();
    if (threadIdx.x < 16) atomicAdd(&out16[threadIdx.x], sh[threadIdx.x]);
}

__global__ void pred_kernel(const float* __restrict__ xa, const int* __restrict__ srcidx,
                            const float* __restrict__ sum16, float* __restrict__ pred, int L) {
    int t = blockIdx.x * blockDim.x + threadIdx.x;
    if (t >= L) return;
    const float* row = xa + (size_t)srcidx[t] * 16;
    float s = 0.f;
#pragma unroll
    for (int k = 0; k < 16; k++) s += row[k] * __ldg(sum16 + k);
    pred[t] = s;
}

// ---------------- host orchestration ----------------
static inline int cdiv(int a, int b) { return (a + b - 1) / b; }

extern "C" void kernel_launch(void* const* d_in, const int* in_sizes, int n_in,
                              void* d_out, int out_size) {
    const float* xAin = (const float*)d_in[0];
    const float* xBin = (const float*)d_in[1];
    const int* ei_ab = (const int*)d_in[2];
    const int* ei_ba = (const int*)d_in[3];
    const int* srcI = (const int*)d_in[4];
    const int* dstI = (const int*)d_in[5];

    const float* Wab[3]  = {(const float*)d_in[6],  (const float*)d_in[14], (const float*)d_in[22]};
    const float* asab[3] = {(const float*)d_in[7],  (const float*)d_in[15], (const float*)d_in[23]};
    const float* adab[3] = {(const float*)d_in[8],  (const float*)d_in[16], (const float*)d_in[24]};
    const float* bab[3]  = {(const float*)d_in[9],  (const float*)d_in[17], (const float*)d_in[25]};
    const float* Wba[3]  = {(const float*)d_in[10], (const float*)d_in[18], (const float*)d_in[26]};
    const float* asba[3] = {(const float*)d_in[11], (const float*)d_in[19], (const float*)d_in[27]};
    const float* adba[3] = {(const float*)d_in[12], (const float*)d_in[20], (const float*)d_in[28]};
    const float* bba[3]  = {(const float*)d_in[13], (const float*)d_in[21], (const float*)d_in[29]};

    float* out = (float*)d_out;
    float* pred = out;
    float* xaOut = out + LPRED;
    float* xbOut = xaOut + (size_t)NA * 16;

    float* F = nullptr;
    int* I = nullptr;
    cudaGetSymbolAddress((void**)&F, g_fpool);
    cudaGetSymbolAddress((void**)&I, g_ipool);

    __half* XAH = (__half*)(F + OFF_XAH);
    __half* XAL = (__half*)(F + OFF_XAL);
    __half* XBH = (__half*)(F + OFF_XBH);
    __half* XBL = (__half*)(F + OFF_XBL);
    float* HABf = F + OFF_HAB;
    float* HBAf = F + OFF_HBA;
    __half* HABh = (__half*)(F + OFF_HAB);
    __half* HBAh = (__half*)(F + OFF_HBA);
    float* SSAB = F + OFF_SSAB;
    float* SSBA = F + OFF_SSBA;
    float* DDAB = F + OFF_DDAB;
    float* DDBA = F + OFF_DDBA;
    float* SV = F + OFF_SV;
    float* SUM16 = F + OFF_SUM16;
    __half* WTABH = (__half*)(F + OFF_WTABH);
    __half* WTABL = (__half*)(F + OFF_WTABL);
    __half* WTBAH = (__half*)(F + OFF_WTBAH);
    __half* WTBAL = (__half*)(F + OFF_WTBAL);

    int* RP2 = I + IOFF_RP2;
    int* CNT2 = I + IOFF_CNT2;
    int* FILL2 = I + IOFF_FILL2;
    int* SRT = I + IOFF_SRT;
    int* BSUM = I + IOFF_BSUM;

    const int FinL[3] = {128, 256, 256};
    const int FoutL[3] = {256, 256, 16};

    // ---- all dv projections upfront: SV + l*512 {+0: ab, +256: ba} ----
    for (int l = 0; l < 3; l++)
        wv2_kernel<<<dim3(cdiv(FinL[l], 8), 2), 256>>>(
            Wab[l], adab[l], SV + l * 512, Wba[l], adba[l], SV + l * 512 + 256,
            FinL[l], FoutL[l]);

    // ---- concatenated CSR build ----
    const int NSEG = NA + NB;
    const int nScanBlk = cdiv(NSEG, 1024);
    cudaMemsetAsync(CNT2, 0, NSEG * sizeof(int), 0);
    hist2_kernel<<<cdiv(2 * NEDGE, 256), 256>>>(ei_ab, ei_ba, CNT2);
    scan1_kernel<<<nScanBlk, 1024>>>(CNT2, RP2, BSUM, NSEG);
    scan2_kernel<<<1, 128>>>(BSUM, nScanBlk);
    scan3_kernel<<<nScanBlk, 1024>>>(RP2, BSUM, NSEG);
    cudaMemsetAsync(FILL2, 0, NSEG * sizeof(int), 0);
    scatter2_kernel<<<cdiv(2 * NEDGE, 256), 256>>>(ei_ab, ei_ba, RP2, FILL2, SRT);

    // ---- layer-1 X split + dd ----
    splitX_kernel<<<cdiv(NA, 8), 256>>>(xAin, XAH, XAL, SV + 256, DDBA, NA);
    splitX_kernel<<<cdiv(NB, 8), 256>>>(xBin, XBH, XBL, SV + 0, DDAB, NB);

    for (int l = 0; l < 3; l++) {
        int Fin = FinL[l];

        if (l < 2) {
            cudaMemsetAsync(SSAB, 0, 2 * NA * sizeof(float), 0);  // SSAB + SSBA
            transpose2split_kernel<<<dim3(256 / 32, Fin / 32, 2), dim3(32, 8)>>>(
                Wab[l], WTABH, WTABL, Wba[l], WTBAH, WTBAL, Fin, 256);
            gemm_f16x3_kernel<<<dim3(cdiv(NA, 128), 2), 256>>>(
                XAH, XAL, WTABH, WTABL, HABh, NA, 256, Fin, asab[l], SSAB);
            gemm_f16x3_kernel<<<dim3(cdiv(NB, 128), 2), 256>>>(
                XBH, XBL, WTBAH, WTBAL, HBAh, NB, 256, Fin, asba[l], SSBA);

            // gat->XB computes dd_ab(l+1); gat->XA computes dd_ba(l+1)
            gat256h_kernel<<<cdiv(NB, 8), 256>>>(RP2, SRT, SSAB, DDAB, HABh, bab[l],
                                                 XBH, XBL, SV + (l + 1) * 512, DDAB, NB);
            gat256h_kernel<<<cdiv(NA, 8), 256>>>(RP2 + NB, SRT, SSBA, DDBA, HBAh, bba[l],
                                                 XAH, XAL, SV + (l + 1) * 512 + 256, DDBA, NA);
        } else {
            gemm_n16_kernel<<<cdiv(NA, 32), 512>>>(XAH, XAL, Wab[l], HABf, NA, asab[l], SSAB);
            gemm_n16_kernel<<<cdiv(NB, 32), 512>>>(XBH, XBL, Wba[l], HBAf, NB, asba[l], SSBA);

            gat16_kernel<<<cdiv(NB, 8), 256>>>(RP2, SRT, SSAB, DDAB, HABf, bab[l], xbOut, NB);
            gat16_kernel<<<cdiv(NA, 8), 256>>>(RP2 + NB, SRT, SSBA, DDBA, HBAf, bba[l], xaOut, NA);
        }
    }

    // ---- readout ----
    cudaMemsetAsync(SUM16, 0, 16 * sizeof(float), 0);
    sumrows16_kernel<<<256, 256>>>(xbOut, dstI, SUM16, LPRED);
    pred_kernel<<<cdiv(LPRED, 256), 256>>>(xaOut, srcI, SUM16, pred, LPRED);
}